// round 10
// baseline (speedup 1.0000x reference)
#include <cuda_runtime.h>
#include <cuda_fp16.h>
#include <cstdint>

// Problem dims
#define NB    4096
#define IN_D  1024
#define NH0   4000
#define NH1   4000
#define NR    2000
#define NOUT  10
#define KP0   4096
#define KP1   8192
#define NPAD  2048
#define N1PAD 4096

#define BASE_THRE 0.1f
#define R_M       3.0f
#define BETA      1.8f

#define SC1   2.44140625e-4f   // 2^-12 fold scale

// ---------------------------------------------------------------------------
// Static device scratch (zero-initialized; pad regions stay zero forever)
// ---------------------------------------------------------------------------
__device__ __align__(256) __half g_Wo[2][(size_t)NPAD * KP0];
__device__ __align__(256) __half g_Wi[2][(size_t)NPAD * KP1];
__device__ __align__(256) __half g_Ah[(size_t)NB * KP1];
__device__ __align__(256) __half g_X[2][(size_t)NB * IN_D];
__device__ __align__(256) __half g_Wf[2][(size_t)N1PAD * IN_D];
__device__ float g_stm2[NH1];
__device__ float g_sta2[NH1];
__device__ float g_bias2[NH1];

__device__ __forceinline__ float sigm(float x) { return 1.0f / (1.0f + expf(-x)); }

__device__ __forceinline__ uint32_t smem_u32(const void* p) {
    uint32_t a;
    asm("{ .reg .u64 t; cvta.to.shared.u64 t, %1; cvt.u32.u64 %0, t; }" : "=r"(a) : "l"(p));
    return a;
}
__device__ __forceinline__ void cp16(uint32_t dst, const void* src) {
    asm volatile("cp.async.cg.shared.global [%0], [%1], 16;" :: "r"(dst), "l"(src) : "memory");
}
#define CP_COMMIT() asm volatile("cp.async.commit_group;" ::: "memory")
#define CP_WAIT1()  asm volatile("cp.async.wait_group 1;" ::: "memory")
#define CP_WAIT2()  asm volatile("cp.async.wait_group 2;" ::: "memory")

__device__ __forceinline__ void ldm_x4(uint32_t& r0, uint32_t& r1, uint32_t& r2, uint32_t& r3,
                                       uint32_t addr) {
    asm volatile("ldmatrix.sync.aligned.m8n8.x4.shared.b16 {%0,%1,%2,%3}, [%4];"
                 : "=r"(r0), "=r"(r1), "=r"(r2), "=r"(r3) : "r"(addr));
}
__device__ __forceinline__ void hmma16816(float* c, const uint32_t* a, uint32_t b0, uint32_t b1) {
    asm volatile(
        "mma.sync.aligned.m16n8k16.row.col.f32.f16.f16.f32 "
        "{%0,%1,%2,%3}, {%4,%5,%6,%7}, {%8,%9}, {%0,%1,%2,%3};"
        : "+f"(c[0]), "+f"(c[1]), "+f"(c[2]), "+f"(c[3])
        : "r"(a[0]), "r"(a[1]), "r"(a[2]), "r"(a[3]), "r"(b0), "r"(b1));
}

__device__ __forceinline__ void split2h(float w, __half& h0, __half& h1) {
    h0 = __float2half(w);
    float r = w - __half2float(h0);
    h1 = __float2half(r * 4096.0f);
}

// XOR-swizzled tile offset: 128 rows x 128B (8 chunks of 16B), conflict-free
__device__ __forceinline__ uint32_t sw(int row, int ch) {
    return (uint32_t)(row * 128 + ((ch ^ (row & 7)) << 4));
}

// ---------------------------------------------------------------------------
// Pre-conversion: all splits + layer2 column params
// ---------------------------------------------------------------------------
__global__ void convPre_kernel(
    const float* __restrict__ rec4out, const float* __restrict__ in2out,
    const float* __restrict__ out2in,  const float* __restrict__ rec4in,
    const float* __restrict__ x2in,    const float* __restrict__ fc_w,
    const float* __restrict__ x_t,
    const float* __restrict__ tau_m2,  const float* __restrict__ tau_adp2,
    const float* __restrict__ rec4out_b, const float* __restrict__ in2out_b,
    const float* __restrict__ out2in_b,  const float* __restrict__ rec4in_b,
    const float* __restrict__ x2in_b)
{
    const long S1 = (long)NR * NR;
    const long S2 = (long)NR * NH0;
    const long SF = (long)NH0 * IN_D;
    const long SX = (long)NB * IN_D;
    long i = (long)blockIdx.x * blockDim.x + threadIdx.x;
    if (i < 4 * S1) {
        int sel = (int)(i / S1);
        long r  = i % S1;
        int n = (int)(r / NR), k = (int)(r % NR);
        float w; size_t dst; int which;
        if (sel == 0)      { w = rec4out[r]; dst = (size_t)n * KP0 + k;        which = 0; }
        else if (sel == 1) { w = in2out[r];  dst = (size_t)n * KP0 + 2048 + k; which = 0; }
        else if (sel == 2) { w = out2in[r];  dst = (size_t)n * KP1 + k;        which = 1; }
        else               { w = rec4in[r];  dst = (size_t)n * KP1 + 2048 + k; which = 1; }
        __half a, b; split2h(w, a, b);
        if (which == 0) { g_Wo[0][dst] = a; g_Wo[1][dst] = b; }
        else            { g_Wi[0][dst] = a; g_Wi[1][dst] = b; }
    } else if (i < 4 * S1 + S2) {
        long r = i - 4 * S1;
        int n = (int)(r / NH0), k = (int)(r % NH0);
        __half a, b; split2h(x2in[r], a, b);
        size_t dst = (size_t)n * KP1 + 4096 + k;
        g_Wi[0][dst] = a; g_Wi[1][dst] = b;
    } else if (i < 4 * S1 + S2 + SF) {
        long r = i - 4 * S1 - S2;
        __half a, b; split2h(fc_w[r], a, b);
        g_Wf[0][r] = a; g_Wf[1][r] = b;
    } else if (i < 4 * S1 + S2 + SF + SX) {
        long r = i - 4 * S1 - S2 - SF;
        __half a, b; split2h(x_t[r], a, b);
        g_X[0][r] = a; g_X[1][r] = b;
    } else if (i < 4 * S1 + S2 + SF + SX + NH1) {
        int g = (int)(i - 4 * S1 - S2 - SF - SX);
        g_stm2[g] = sigm(tau_m2[g]);
        g_sta2[g] = sigm(tau_adp2[g]);
        g_bias2[g] = (g < NR) ? (rec4out_b[g] + in2out_b[g])
                              : (x2in_b[g - NR] + rec4in_b[g - NR] + out2in_b[g - NR]);
    }
}

// Pack spikes into fp16 A: [spk_out|0][spk_in|0][spk1n|0]
__global__ void convA_kernel(const float* __restrict__ spk2, const float* __restrict__ spk1n)
{
    const long T1 = (long)NB * NH1;
    long i = (long)blockIdx.x * blockDim.x + threadIdx.x;
    if (i < T1) {
        int b = (int)(i / NH1), k = (int)(i % NH1);
        g_Ah[(size_t)b * KP1 + (k < NR ? k : k + 48)] = __float2half(spk2[i]);
    } else if (i < 2 * T1) {
        long r = i - T1;
        int b = (int)(r / NH0), k = (int)(r % NH0);
        g_Ah[(size_t)b * KP1 + 4096 + k] = __float2half(spk1n[r]);
    }
}

#define TSZ 16384   // tile bytes: 128 rows x 128B (BK=64 fp16)

// ---------------------------------------------------------------------------
// GEMM1: HMMA cross-split (x0w0 -> acc0; x0w1+x1w0 -> accS)
// CTA 128x128, 256 thr (8 warps: 2 wm x 4 wn, warp tile 64x32), BK=64,
// 3 stages, XOR swizzle. Stage: X0,X1,W0,W1 each 16KB = 64KB; 3 = 192KB.
// ---------------------------------------------------------------------------
#define STG1    (4 * TSZ)
#define SMEM_G1 (3 * STG1)

__global__ void __launch_bounds__(256, 1) gemm1_h2_kernel(
    const float* __restrict__ fc_b,
    const float* __restrict__ mem1, const float* __restrict__ spk1, const float* __restrict__ b1,
    const float* __restrict__ tau_m1, const float* __restrict__ tau_adp1,
    float* __restrict__ out_mem1, float* __restrict__ out_spk1, float* __restrict__ out_b1)
{
    extern __shared__ char smem[];
    const uint32_t sb = smem_u32(smem);
    const int tid  = threadIdx.x;
    const int wid  = tid >> 5;
    const int lane = tid & 31;
    const int m0   = blockIdx.x * 128;
    const int n0   = blockIdx.y * 128;
    const int C    = IN_D / 64;     // 16 chunks

    const __half* src[4] = {
        &g_X[0][(size_t)m0 * IN_D], &g_X[1][(size_t)m0 * IN_D],
        &g_Wf[0][(size_t)n0 * IN_D], &g_Wf[1][(size_t)n0 * IN_D] };

    // loader: 4096 cp16 per chunk, 16 per thread
    auto issue = [&](int c) {
        const uint32_t dst = sb + (c % 3) * STG1;
        const size_t ko = (size_t)c * 64;
        #pragma unroll
        for (int j = 0; j < 16; j++) {
            const int i = tid + j * 256;
            const int row = i >> 3, ch = i & 7;     // row 0..511
            const int q = row >> 7, r = row & 127;
            cp16(dst + q * TSZ + sw(r, ch),
                 src[q] + (size_t)r * IN_D + ko + ch * 8);
        }
        CP_COMMIT();
    };

    const int wm = wid >> 2;     // 0..1  (64 m-rows each)
    const int wn = wid & 3;      // 0..3  (32 n-cols each)
    const int lrow = lane & 15;
    const int lch  = lane >> 4;

    float acc0[4][4][4], accS[4][4][4];
    #pragma unroll
    for (int mi = 0; mi < 4; mi++)
        #pragma unroll
        for (int ni = 0; ni < 4; ni++)
            #pragma unroll
            for (int r = 0; r < 4; r++) { acc0[mi][ni][r] = 0.f; accS[mi][ni][r] = 0.f; }

    issue(0); issue(1);

    for (int c = 0; c < C; c++) {
        CP_WAIT1();
        __syncthreads();
        if (c + 2 < C) issue(c + 2);
        else CP_COMMIT();

        const uint32_t stb = sb + (c % 3) * STG1;
        #pragma unroll
        for (int ks = 0; ks < 4; ks++) {
            const int ch = 2 * ks + lch;
            uint32_t a0[4][4], a1[4][4];
            #pragma unroll
            for (int mi = 0; mi < 4; mi++) {
                const int row = wm * 64 + mi * 16 + lrow;
                ldm_x4(a0[mi][0], a0[mi][1], a0[mi][2], a0[mi][3], stb + sw(row, ch));
                ldm_x4(a1[mi][0], a1[mi][1], a1[mi][2], a1[mi][3], stb + TSZ + sw(row, ch));
            }
            uint32_t b0[4][2], b1[4][2];
            #pragma unroll
            for (int nj = 0; nj < 2; nj++) {
                const int row = wn * 32 + nj * 16 + lrow;
                uint32_t r0, r1, r2, r3;
                ldm_x4(r0, r1, r2, r3, stb + 2 * TSZ + sw(row, ch));
                b0[nj * 2 + 0][0] = r0; b0[nj * 2 + 0][1] = r2;
                b0[nj * 2 + 1][0] = r1; b0[nj * 2 + 1][1] = r3;
                ldm_x4(r0, r1, r2, r3, stb + 3 * TSZ + sw(row, ch));
                b1[nj * 2 + 0][0] = r0; b1[nj * 2 + 0][1] = r2;
                b1[nj * 2 + 1][0] = r1; b1[nj * 2 + 1][1] = r3;
            }
            #pragma unroll
            for (int mi = 0; mi < 4; mi++)
                #pragma unroll
                for (int ni = 0; ni < 4; ni++) {
                    hmma16816(acc0[mi][ni], a0[mi], b0[ni][0], b0[ni][1]);
                    hmma16816(accS[mi][ni], a0[mi], b1[ni][0], b1[ni][1]);
                    hmma16816(accS[mi][ni], a1[mi], b0[ni][0], b0[ni][1]);
                }
        }
    }

    const int erow = lane >> 2;
    const int ecol = (lane & 3) * 2;
    #pragma unroll
    for (int mi = 0; mi < 4; mi++) {
        #pragma unroll
        for (int r2i = 0; r2i < 2; r2i++) {
            const int m = m0 + wm * 64 + mi * 16 + erow + r2i * 8;
            const size_t rowo = (size_t)m * NH0;
            #pragma unroll
            for (int ni = 0; ni < 4; ni++) {
                #pragma unroll
                for (int cc = 0; cc < 2; cc++) {
                    const int n = n0 + wn * 32 + ni * 8 + ecol + cc;
                    if (n >= NH0) continue;
                    const size_t idx = rowo + n;
                    const float inp = acc0[mi][ni][r2i * 2 + cc]
                                    + SC1 * accS[mi][ni][r2i * 2 + cc]
                                    + fc_b[n];
                    const float tm = sigm(tau_m1[n]), ta = sigm(tau_adp1[n]);
                    const float sp = spk1[idx];
                    const float bb = ta * b1[idx] + (1.f - ta) * sp;
                    const float thre = BASE_THRE + BETA * bb;
                    const float mem = mem1[idx] * tm + (1.f - tm) * R_M * inp - thre * sp;
                    out_mem1[idx] = mem;
                    out_spk1[idx] = (mem - thre) > 0.f ? 1.f : 0.f;
                    out_b1[idx]   = bb;
                }
            }
        }
    }
}

// ---------------------------------------------------------------------------
// GEMM2: HMMA 2-term weight split. CTA 128x128, 256 thr (8 warps: 2x4,
// warp tile 64x32), BK=64, 4 stages, XOR swizzle.
// Stage: A,W0,W1 each 16KB = 48KB; 4 stages = 192KB.  grid: (32, 16, 2)
// ---------------------------------------------------------------------------
#define STG2    (3 * TSZ)
#define SMEM_G2 (4 * STG2)

__global__ void __launch_bounds__(256, 1) gemm2_h2_kernel(
    const float* __restrict__ spk2, const float* __restrict__ mem2,
    const float* __restrict__ b2,
    float* __restrict__ out_mem2, float* __restrict__ out_spk2, float* __restrict__ out_b2)
{
    extern __shared__ char smem[];
    const uint32_t sb = smem_u32(smem);
    const int tid  = threadIdx.x;
    const int wid  = tid >> 5;
    const int lane = tid & 31;
    const int mode = blockIdx.z;
    const int m0   = blockIdx.x * 128;
    const int n0   = blockIdx.y * 128;

    const int Kpad = mode ? KP1 : KP0;
    const int C    = Kpad / 64;
    const __half* A0 = g_Ah + (size_t)m0 * KP1;
    const __half* W0 = (mode ? &g_Wi[0][0] : &g_Wo[0][0]) + (size_t)n0 * Kpad;
    const __half* W1 = (mode ? &g_Wi[1][0] : &g_Wo[1][0]) + (size_t)n0 * Kpad;

    // loader: 3072 cp16 per chunk, 12 per thread
    auto issue = [&](int c) {
        const uint32_t dst = sb + (c & 3) * STG2;
        const size_t ko = (size_t)c * 64;
        #pragma unroll
        for (int j = 0; j < 12; j++) {
            const int i = tid + j * 256;
            const int row = i >> 3, ch = i & 7;     // row 0..383
            const int q = row >> 7, r = row & 127;
            const __half* s = (q == 0) ? A0 : (q == 1 ? W0 : W1);
            const size_t stride = (q == 0) ? KP1 : Kpad;
            cp16(dst + q * TSZ + sw(r, ch), s + (size_t)r * stride + ko + ch * 8);
        }
        CP_COMMIT();
    };

    const int wm = wid >> 2;     // 0..1
    const int wn = wid & 3;      // 0..3
    const int lrow = lane & 15;
    const int lch  = lane >> 4;

    float acc0[4][4][4], acc1[4][4][4];
    #pragma unroll
    for (int mi = 0; mi < 4; mi++)
        #pragma unroll
        for (int ni = 0; ni < 4; ni++)
            #pragma unroll
            for (int r = 0; r < 4; r++) { acc0[mi][ni][r] = 0.f; acc1[mi][ni][r] = 0.f; }

    issue(0); issue(1); issue(2);

    for (int c = 0; c < C; c++) {
        CP_WAIT2();
        __syncthreads();
        if (c + 3 < C) issue(c + 3);
        else CP_COMMIT();

        const uint32_t stb = sb + (c & 3) * STG2;
        #pragma unroll
        for (int ks = 0; ks < 4; ks++) {
            const int ch = 2 * ks + lch;
            uint32_t a[4][4];
            #pragma unroll
            for (int mi = 0; mi < 4; mi++) {
                const int row = wm * 64 + mi * 16 + lrow;
                ldm_x4(a[mi][0], a[mi][1], a[mi][2], a[mi][3], stb + sw(row, ch));
            }
            #pragma unroll
            for (int t = 0; t < 2; t++) {
                uint32_t b[4][2];
                #pragma unroll
                for (int nj = 0; nj < 2; nj++) {
                    const int row = wn * 32 + nj * 16 + lrow;
                    uint32_t r0, r1, r2, r3;
                    ldm_x4(r0, r1, r2, r3, stb + (1 + t) * TSZ + sw(row, ch));
                    b[nj * 2 + 0][0] = r0; b[nj * 2 + 0][1] = r2;
                    b[nj * 2 + 1][0] = r1; b[nj * 2 + 1][1] = r3;
                }
                float (*acc)[4][4] = t ? acc1 : acc0;
                #pragma unroll
                for (int mi = 0; mi < 4; mi++)
                    #pragma unroll
                    for (int ni = 0; ni < 4; ni++)
                        hmma16816(acc[mi][ni], a[mi], b[ni][0], b[ni][1]);
            }
        }
    }

    const int erow = lane >> 2;
    const int ecol = (lane & 3) * 2;
    #pragma unroll
    for (int mi = 0; mi < 4; mi++) {
        #pragma unroll
        for (int r2i = 0; r2i < 2; r2i++) {
            const int m = m0 + wm * 64 + mi * 16 + erow + r2i * 8;
            const size_t rowo = (size_t)m * NH1;
            #pragma unroll
            for (int ni = 0; ni < 4; ni++) {
                #pragma unroll
                for (int cc = 0; cc < 2; cc++) {
                    const int nl = n0 + wn * 32 + ni * 8 + ecol + cc;
                    if (nl >= NR) continue;
                    const int g = mode * NR + nl;
                    const size_t idx = rowo + g;
                    const float v = acc0[mi][ni][r2i * 2 + cc]
                                  + SC1 * acc1[mi][ni][r2i * 2 + cc]
                                  + g_bias2[g];
                    const float tm = g_stm2[g], ta = g_sta2[g];
                    const float sp = spk2[idx];
                    const float bb = ta * b2[idx] + (1.f - ta) * sp;
                    const float thre = BASE_THRE + BETA * bb;
                    const float mem = mem2[idx] * tm + (1.f - tm) * R_M * v - thre * sp;
                    out_mem2[idx] = mem;
                    out_spk2[idx] = (mem - thre) > 0.f ? 1.f : 0.f;
                    out_b2[idx]   = bb;
                }
            }
        }
    }
}

// ---------------------------------------------------------------------------
// Head: pooling + mem_out update + log_softmax
// ---------------------------------------------------------------------------
__global__ void head_kernel(
    const float* __restrict__ spk2n, const float* __restrict__ mem_out,
    const float* __restrict__ out_tau_m,
    float* __restrict__ log_sm, float* __restrict__ mem_out_n)
{
    __shared__ float xo[NOUT];
    const int row = blockIdx.x;
    const int w = threadIdx.x >> 5, lane = threadIdx.x & 31;
    float s = 0.f;
    const float* p = spk2n + (size_t)row * NH1 + w * 200;
    for (int i = lane; i < 200; i += 32) s += p[i];
    #pragma unroll
    for (int o = 16; o > 0; o >>= 1) s += __shfl_down_sync(0xffffffffu, s, o);
    if (lane == 0) xo[w] = s;
    __syncthreads();
    if (threadIdx.x == 0) {
        float v[NOUT];
        float mx = -1e30f;
        #pragma unroll
        for (int o = 0; o < NOUT; o++) {
            const float m = mem_out[(size_t)row * NOUT + o];
            const float mo = m + (xo[o] - m) * sigm(out_tau_m[o]);
            v[o] = mo; mem_out_n[(size_t)row * NOUT + o] = mo;
            mx = fmaxf(mx, mo);
        }
        float se = 0.f;
        #pragma unroll
        for (int o = 0; o < NOUT; o++) se += expf(v[o] - mx);
        const float lse = mx + logf(se);
        #pragma unroll
        for (int o = 0; o < NOUT; o++) log_sm[(size_t)row * NOUT + o] = v[o] - lse;
    }
}

// ---------------------------------------------------------------------------
// Launch
// ---------------------------------------------------------------------------
extern "C" void kernel_launch(void* const* d_in, const int* in_sizes, int n_in,
                              void* d_out, int out_size)
{
    const float* x_t       = (const float*)d_in[0];
    const float* mem1      = (const float*)d_in[1];
    const float* spk1      = (const float*)d_in[2];
    const float* b1        = (const float*)d_in[3];
    const float* mem2      = (const float*)d_in[4];
    const float* spk2      = (const float*)d_in[5];
    const float* b2        = (const float*)d_in[6];
    const float* mem_out   = (const float*)d_in[7];
    const float* fc_w      = (const float*)d_in[8];
    const float* fc_b      = (const float*)d_in[9];
    const float* tau_adp1  = (const float*)d_in[10];
    const float* tau_m1    = (const float*)d_in[11];
    const float* x2in_w    = (const float*)d_in[12];
    const float* x2in_b    = (const float*)d_in[13];
    const float* rec4in_w  = (const float*)d_in[14];
    const float* rec4in_b  = (const float*)d_in[15];
    const float* in2out_w  = (const float*)d_in[16];
    const float* in2out_b  = (const float*)d_in[17];
    const float* rec4out_w = (const float*)d_in[18];
    const float* rec4out_b = (const float*)d_in[19];
    const float* out2in_w  = (const float*)d_in[20];
    const float* out2in_b  = (const float*)d_in[21];
    const float* tau_adp2  = (const float*)d_in[22];
    const float* tau_m2    = (const float*)d_in[23];
    const float* out_tau_m = (const float*)d_in[24];

    float* out = (float*)d_out;
    const size_t BH = (size_t)NB * NH0;
    float* log_sm    = out;
    float* mem1n     = out + (size_t)NB * NOUT;
    float* spk1n     = mem1n + BH;
    float* b1n       = spk1n + BH;
    float* mem2n     = b1n + BH;
    float* spk2n     = mem2n + BH;
    float* b2n       = spk2n + BH;
    float* mem_out_n = b2n + BH;

    cudaFuncSetAttribute(gemm1_h2_kernel, cudaFuncAttributeMaxDynamicSharedMemorySize,
                         SMEM_G1);
    cudaFuncSetAttribute(gemm2_h2_kernel, cudaFuncAttributeMaxDynamicSharedMemorySize,
                         SMEM_G2);

    {
        const long T = 4L * NR * NR + (long)NR * NH0 + (long)NH0 * IN_D
                     + (long)NB * IN_D + NH1;
        convPre_kernel<<<(int)((T + 255) / 256), 256>>>(
            rec4out_w, in2out_w, out2in_w, rec4in_w, x2in_w, fc_w, x_t,
            tau_m2, tau_adp2, rec4out_b, in2out_b, out2in_b, rec4in_b, x2in_b);
    }

    gemm1_h2_kernel<<<dim3(32, 32), 256, SMEM_G1>>>(
        fc_b, mem1, spk1, b1, tau_m1, tau_adp1, mem1n, spk1n, b1n);

    {
        const long T = 2L * NB * NH1;
        convA_kernel<<<(int)((T + 255) / 256), 256>>>(spk2, spk1n);
    }

    gemm2_h2_kernel<<<dim3(32, 16, 2), 256, SMEM_G2>>>(
        spk2, mem2, b2, mem2n, spk2n, b2n);

    head_kernel<<<NB, 320>>>(spk2n, mem_out, out_tau_m, log_sm, mem_out_n);
}

// round 12
// speedup vs baseline: 1.0874x; 1.0874x over previous
#include <cuda_runtime.h>
#include <cuda_fp16.h>
#include <cstdint>

// Problem dims
#define NB    4096
#define IN_D  1024
#define NH0   4000
#define NH1   4000
#define NR    2000
#define NOUT  10
#define KP0   4096
#define KP1   8192
#define NPAD  2048
#define N1PAD 4096

#define BASE_THRE 0.1f
#define R_M       3.0f
#define BETA      1.8f

#define SC1   2.44140625e-4f   // 2^-12 fold scale

// ---------------------------------------------------------------------------
// Static device scratch (zero-initialized; pad regions stay zero forever)
// ---------------------------------------------------------------------------
__device__ __align__(256) __half g_Wo[2][(size_t)NPAD * KP0];
__device__ __align__(256) __half g_Wi[2][(size_t)NPAD * KP1];
__device__ __align__(256) __half g_Ah[(size_t)NB * KP1];
__device__ __align__(256) __half g_X[2][(size_t)NB * IN_D];
__device__ __align__(256) __half g_Wf[2][(size_t)N1PAD * IN_D];
__device__ float g_stm1[NH0];
__device__ float g_sta1[NH0];
__device__ float g_stm2[NH1];
__device__ float g_sta2[NH1];
__device__ float g_bias2[NH1];

__device__ __forceinline__ float sigm(float x) { return 1.0f / (1.0f + expf(-x)); }

__device__ __forceinline__ uint32_t smem_u32(const void* p) {
    uint32_t a;
    asm("{ .reg .u64 t; cvta.to.shared.u64 t, %1; cvt.u32.u64 %0, t; }" : "=r"(a) : "l"(p));
    return a;
}
__device__ __forceinline__ void cp16(uint32_t dst, const void* src) {
    asm volatile("cp.async.cg.shared.global [%0], [%1], 16;" :: "r"(dst), "l"(src) : "memory");
}
#define CP_COMMIT() asm volatile("cp.async.commit_group;" ::: "memory")
#define CP_WAIT1()  asm volatile("cp.async.wait_group 1;" ::: "memory")
#define CP_WAIT2()  asm volatile("cp.async.wait_group 2;" ::: "memory")

__device__ __forceinline__ void ldm_x4(uint32_t& r0, uint32_t& r1, uint32_t& r2, uint32_t& r3,
                                       uint32_t addr) {
    asm volatile("ldmatrix.sync.aligned.m8n8.x4.shared.b16 {%0,%1,%2,%3}, [%4];"
                 : "=r"(r0), "=r"(r1), "=r"(r2), "=r"(r3) : "r"(addr));
}
__device__ __forceinline__ void hmma16816(float* c, const uint32_t* a, uint32_t b0, uint32_t b1) {
    asm volatile(
        "mma.sync.aligned.m16n8k16.row.col.f32.f16.f16.f32 "
        "{%0,%1,%2,%3}, {%4,%5,%6,%7}, {%8,%9}, {%0,%1,%2,%3};"
        : "+f"(c[0]), "+f"(c[1]), "+f"(c[2]), "+f"(c[3])
        : "r"(a[0]), "r"(a[1]), "r"(a[2]), "r"(a[3]), "r"(b0), "r"(b1));
}

__device__ __forceinline__ void split2h(float w, __half& h0, __half& h1) {
    h0 = __float2half(w);
    float r = w - __half2float(h0);
    h1 = __float2half(r * 4096.0f);
}

// XOR-swizzled tile offset: 128 rows x 128B (8 chunks of 16B), conflict-free
__device__ __forceinline__ uint32_t sw(int row, int ch) {
    return (uint32_t)(row * 128 + ((ch ^ (row & 7)) << 4));
}

// ---------------------------------------------------------------------------
// Pre-conversion: all splits + column params for BOTH layers
// ---------------------------------------------------------------------------
__global__ void convPre_kernel(
    const float* __restrict__ rec4out, const float* __restrict__ in2out,
    const float* __restrict__ out2in,  const float* __restrict__ rec4in,
    const float* __restrict__ x2in,    const float* __restrict__ fc_w,
    const float* __restrict__ x_t,
    const float* __restrict__ tau_m1,  const float* __restrict__ tau_adp1,
    const float* __restrict__ tau_m2,  const float* __restrict__ tau_adp2,
    const float* __restrict__ rec4out_b, const float* __restrict__ in2out_b,
    const float* __restrict__ out2in_b,  const float* __restrict__ rec4in_b,
    const float* __restrict__ x2in_b)
{
    const long S1 = (long)NR * NR;
    const long S2 = (long)NR * NH0;
    const long SF = (long)NH0 * IN_D;
    const long SX = (long)NB * IN_D;
    long i = (long)blockIdx.x * blockDim.x + threadIdx.x;
    if (i < 4 * S1) {
        int sel = (int)(i / S1);
        long r  = i % S1;
        int n = (int)(r / NR), k = (int)(r % NR);
        float w; size_t dst; int which;
        if (sel == 0)      { w = rec4out[r]; dst = (size_t)n * KP0 + k;        which = 0; }
        else if (sel == 1) { w = in2out[r];  dst = (size_t)n * KP0 + 2048 + k; which = 0; }
        else if (sel == 2) { w = out2in[r];  dst = (size_t)n * KP1 + k;        which = 1; }
        else               { w = rec4in[r];  dst = (size_t)n * KP1 + 2048 + k; which = 1; }
        __half a, b; split2h(w, a, b);
        if (which == 0) { g_Wo[0][dst] = a; g_Wo[1][dst] = b; }
        else            { g_Wi[0][dst] = a; g_Wi[1][dst] = b; }
    } else if (i < 4 * S1 + S2) {
        long r = i - 4 * S1;
        int n = (int)(r / NH0), k = (int)(r % NH0);
        __half a, b; split2h(x2in[r], a, b);
        size_t dst = (size_t)n * KP1 + 4096 + k;
        g_Wi[0][dst] = a; g_Wi[1][dst] = b;
    } else if (i < 4 * S1 + S2 + SF) {
        long r = i - 4 * S1 - S2;
        __half a, b; split2h(fc_w[r], a, b);
        g_Wf[0][r] = a; g_Wf[1][r] = b;
    } else if (i < 4 * S1 + S2 + SF + SX) {
        long r = i - 4 * S1 - S2 - SF;
        __half a, b; split2h(x_t[r], a, b);
        g_X[0][r] = a; g_X[1][r] = b;
    } else if (i < 4 * S1 + S2 + SF + SX + NH1) {
        int g = (int)(i - 4 * S1 - S2 - SF - SX);
        g_stm2[g] = sigm(tau_m2[g]);
        g_sta2[g] = sigm(tau_adp2[g]);
        g_bias2[g] = (g < NR) ? (rec4out_b[g] + in2out_b[g])
                              : (x2in_b[g - NR] + rec4in_b[g - NR] + out2in_b[g - NR]);
    } else if (i < 4 * S1 + S2 + SF + SX + NH1 + NH0) {
        int g = (int)(i - 4 * S1 - S2 - SF - SX - NH1);
        g_stm1[g] = sigm(tau_m1[g]);
        g_sta1[g] = sigm(tau_adp1[g]);
    }
}

// Pack spk2 into fp16 A: [spk_out|0][spk_in|0]  (spk1n part written by gemm1)
__global__ void convA_kernel(const float* __restrict__ spk2)
{
    const long T1 = (long)NB * NH1;
    long i = (long)blockIdx.x * blockDim.x + threadIdx.x;
    if (i < T1) {
        int b = (int)(i / NH1), k = (int)(i % NH1);
        g_Ah[(size_t)b * KP1 + (k < NR ? k : k + 48)] = __float2half(spk2[i]);
    }
}

#define TSZ 16384   // tile bytes: 128 rows x 128B (BK=64 fp16)

// ---------------------------------------------------------------------------
// GEMM1: HMMA cross-split (x0w0 -> acc0; x0w1+x1w0 -> accS)
// CTA 128x128, 512 thr (16 warps 4x4), BK=64, 3 stages, XOR swizzle.
// Stage: X0,X1,W0,W1 each 16KB = 64KB; 3 stages = 192KB.
// Epilogue also writes fp16 spikes into g_Ah (k-slot 4096+n).
// ---------------------------------------------------------------------------
#define STG1    (4 * TSZ)
#define SMEM_G1 (3 * STG1)

__global__ void __launch_bounds__(512, 1) gemm1_h2_kernel(
    const float* __restrict__ fc_b,
    const float* __restrict__ mem1, const float* __restrict__ spk1, const float* __restrict__ b1,
    float* __restrict__ out_mem1, float* __restrict__ out_spk1, float* __restrict__ out_b1)
{
    extern __shared__ char smem[];
    const uint32_t sb = smem_u32(smem);
    const int tid  = threadIdx.x;
    const int wid  = tid >> 5;
    const int lane = tid & 31;
    const int m0   = blockIdx.x * 128;
    const int n0   = blockIdx.y * 128;
    const int C    = IN_D / 64;     // 16 chunks

    const __half* src[4] = {
        &g_X[0][(size_t)m0 * IN_D], &g_X[1][(size_t)m0 * IN_D],
        &g_Wf[0][(size_t)n0 * IN_D], &g_Wf[1][(size_t)n0 * IN_D] };

    auto issue = [&](int c) {
        const uint32_t dst = sb + (c % 3) * STG1;
        const size_t ko = (size_t)c * 64;
        #pragma unroll
        for (int j = 0; j < 8; j++) {
            const int i = tid + j * 512;
            const int row = i >> 3, ch = i & 7;     // row 0..511
            const int q = row >> 7, r = row & 127;
            cp16(dst + q * TSZ + sw(r, ch),
                 src[q] + (size_t)r * IN_D + ko + ch * 8);
        }
        CP_COMMIT();
    };

    const int wm = wid >> 2;     // 0..3
    const int wn = wid & 3;      // 0..3
    const int lrow = lane & 15;
    const int lch  = lane >> 4;

    float acc0[2][4][4], accS[2][4][4];
    #pragma unroll
    for (int mi = 0; mi < 2; mi++)
        #pragma unroll
        for (int ni = 0; ni < 4; ni++)
            #pragma unroll
            for (int r = 0; r < 4; r++) { acc0[mi][ni][r] = 0.f; accS[mi][ni][r] = 0.f; }

    issue(0); issue(1);

    for (int c = 0; c < C; c++) {
        CP_WAIT1();
        __syncthreads();
        if (c + 2 < C) issue(c + 2);
        else CP_COMMIT();

        const uint32_t stb = sb + (c % 3) * STG1;
        #pragma unroll
        for (int ks = 0; ks < 4; ks++) {
            const int ch = 2 * ks + lch;
            uint32_t a0[2][4], a1[2][4];
            #pragma unroll
            for (int mi = 0; mi < 2; mi++) {
                const int row = wm * 32 + mi * 16 + lrow;
                ldm_x4(a0[mi][0], a0[mi][1], a0[mi][2], a0[mi][3], stb + sw(row, ch));
                ldm_x4(a1[mi][0], a1[mi][1], a1[mi][2], a1[mi][3], stb + TSZ + sw(row, ch));
            }
            uint32_t b0[4][2], b1[4][2];
            #pragma unroll
            for (int nj = 0; nj < 2; nj++) {
                const int row = wn * 32 + nj * 16 + lrow;
                uint32_t r0, r1, r2, r3;
                ldm_x4(r0, r1, r2, r3, stb + 2 * TSZ + sw(row, ch));
                b0[nj * 2 + 0][0] = r0; b0[nj * 2 + 0][1] = r2;
                b0[nj * 2 + 1][0] = r1; b0[nj * 2 + 1][1] = r3;
                ldm_x4(r0, r1, r2, r3, stb + 3 * TSZ + sw(row, ch));
                b1[nj * 2 + 0][0] = r0; b1[nj * 2 + 0][1] = r2;
                b1[nj * 2 + 1][0] = r1; b1[nj * 2 + 1][1] = r3;
            }
            #pragma unroll
            for (int mi = 0; mi < 2; mi++)
                #pragma unroll
                for (int ni = 0; ni < 4; ni++) {
                    hmma16816(acc0[mi][ni], a0[mi], b0[ni][0], b0[ni][1]);
                    hmma16816(accS[mi][ni], a0[mi], b1[ni][0], b1[ni][1]);
                    hmma16816(accS[mi][ni], a1[mi], b0[ni][0], b0[ni][1]);
                }
        }
    }

    const int erow = lane >> 2;
    const int ecol = (lane & 3) * 2;
    #pragma unroll
    for (int mi = 0; mi < 2; mi++) {
        #pragma unroll
        for (int r2i = 0; r2i < 2; r2i++) {
            const int m = m0 + wm * 32 + mi * 16 + erow + r2i * 8;
            const size_t rowo = (size_t)m * NH0;
            const size_t arow = (size_t)m * KP1 + 4096;
            #pragma unroll
            for (int ni = 0; ni < 4; ni++) {
                #pragma unroll
                for (int cc = 0; cc < 2; cc++) {
                    const int n = n0 + wn * 32 + ni * 8 + ecol + cc;
                    if (n >= NH0) continue;
                    const size_t idx = rowo + n;
                    const float inp = acc0[mi][ni][r2i * 2 + cc]
                                    + SC1 * accS[mi][ni][r2i * 2 + cc]
                                    + fc_b[n];
                    const float tm = g_stm1[n], ta = g_sta1[n];
                    const float sp = spk1[idx];
                    const float bb = ta * b1[idx] + (1.f - ta) * sp;
                    const float thre = BASE_THRE + BETA * bb;
                    const float mem = mem1[idx] * tm + (1.f - tm) * R_M * inp - thre * sp;
                    const float spn = (mem - thre) > 0.f ? 1.f : 0.f;
                    out_mem1[idx] = mem;
                    out_spk1[idx] = spn;
                    out_b1[idx]   = bb;
                    g_Ah[arow + n] = __float2half(spn);
                }
            }
        }
    }
}

// ---------------------------------------------------------------------------
// GEMM2: HMMA 2-term weight split. CTA 128x128, 512 thr (16 warps 4x4),
// BK=64, 4 stages, XOR swizzle. Stage: A,W0,W1 each 16KB = 48KB; 4 = 192KB.
// grid: (32 m, 16 n, 2 modes)
// ---------------------------------------------------------------------------
#define STG2    (3 * TSZ)
#define SMEM_G2 (4 * STG2)

__global__ void __launch_bounds__(512, 1) gemm2_h2_kernel(
    const float* __restrict__ spk2, const float* __restrict__ mem2,
    const float* __restrict__ b2,
    float* __restrict__ out_mem2, float* __restrict__ out_spk2, float* __restrict__ out_b2)
{
    extern __shared__ char smem[];
    const uint32_t sb = smem_u32(smem);
    const int tid  = threadIdx.x;
    const int wid  = tid >> 5;
    const int lane = tid & 31;
    const int mode = blockIdx.z;
    const int m0   = blockIdx.x * 128;
    const int n0   = blockIdx.y * 128;

    const int Kpad = mode ? KP1 : KP0;
    const int C    = Kpad / 64;
    const __half* A0 = g_Ah + (size_t)m0 * KP1;
    const __half* W0 = (mode ? &g_Wi[0][0] : &g_Wo[0][0]) + (size_t)n0 * Kpad;
    const __half* W1 = (mode ? &g_Wi[1][0] : &g_Wo[1][0]) + (size_t)n0 * Kpad;

    auto issue = [&](int c) {
        const uint32_t dst = sb + (c & 3) * STG2;
        const size_t ko = (size_t)c * 64;
        #pragma unroll
        for (int j = 0; j < 6; j++) {
            const int i = tid + j * 512;
            const int row = i >> 3, ch = i & 7;     // row 0..383
            const int q = row >> 7, r = row & 127;
            const __half* s = (q == 0) ? A0 : (q == 1 ? W0 : W1);
            const size_t stride = (q == 0) ? KP1 : Kpad;
            cp16(dst + q * TSZ + sw(r, ch), s + (size_t)r * stride + ko + ch * 8);
        }
        CP_COMMIT();
    };

    const int wm = wid >> 2;
    const int wn = wid & 3;
    const int lrow = lane & 15;
    const int lch  = lane >> 4;

    float acc0[2][4][4], acc1[2][4][4];
    #pragma unroll
    for (int mi = 0; mi < 2; mi++)
        #pragma unroll
        for (int ni = 0; ni < 4; ni++)
            #pragma unroll
            for (int r = 0; r < 4; r++) { acc0[mi][ni][r] = 0.f; acc1[mi][ni][r] = 0.f; }

    issue(0); issue(1); issue(2);

    for (int c = 0; c < C; c++) {
        CP_WAIT2();
        __syncthreads();
        if (c + 3 < C) issue(c + 3);
        else CP_COMMIT();

        const uint32_t stb = sb + (c & 3) * STG2;
        #pragma unroll
        for (int ks = 0; ks < 4; ks++) {
            const int ch = 2 * ks + lch;
            uint32_t a[2][4];
            #pragma unroll
            for (int mi = 0; mi < 2; mi++) {
                const int row = wm * 32 + mi * 16 + lrow;
                ldm_x4(a[mi][0], a[mi][1], a[mi][2], a[mi][3], stb + sw(row, ch));
            }
            #pragma unroll
            for (int t = 0; t < 2; t++) {
                uint32_t b[4][2];
                #pragma unroll
                for (int nj = 0; nj < 2; nj++) {
                    const int row = wn * 32 + nj * 16 + lrow;
                    uint32_t r0, r1, r2, r3;
                    ldm_x4(r0, r1, r2, r3, stb + (1 + t) * TSZ + sw(row, ch));
                    b[nj * 2 + 0][0] = r0; b[nj * 2 + 0][1] = r2;
                    b[nj * 2 + 1][0] = r1; b[nj * 2 + 1][1] = r3;
                }
                float (*acc)[4][4] = t ? acc1 : acc0;
                #pragma unroll
                for (int mi = 0; mi < 2; mi++)
                    #pragma unroll
                    for (int ni = 0; ni < 4; ni++)
                        hmma16816(acc[mi][ni], a[mi], b[ni][0], b[ni][1]);
            }
        }
    }

    const int erow = lane >> 2;
    const int ecol = (lane & 3) * 2;
    #pragma unroll
    for (int mi = 0; mi < 2; mi++) {
        #pragma unroll
        for (int r2i = 0; r2i < 2; r2i++) {
            const int m = m0 + wm * 32 + mi * 16 + erow + r2i * 8;
            const size_t rowo = (size_t)m * NH1;
            #pragma unroll
            for (int ni = 0; ni < 4; ni++) {
                #pragma unroll
                for (int cc = 0; cc < 2; cc++) {
                    const int nl = n0 + wn * 32 + ni * 8 + ecol + cc;
                    if (nl >= NR) continue;
                    const int g = mode * NR + nl;
                    const size_t idx = rowo + g;
                    const float v = acc0[mi][ni][r2i * 2 + cc]
                                  + SC1 * acc1[mi][ni][r2i * 2 + cc]
                                  + g_bias2[g];
                    const float tm = g_stm2[g], ta = g_sta2[g];
                    const float sp = spk2[idx];
                    const float bb = ta * b2[idx] + (1.f - ta) * sp;
                    const float thre = BASE_THRE + BETA * bb;
                    const float mem = mem2[idx] * tm + (1.f - tm) * R_M * v - thre * sp;
                    out_mem2[idx] = mem;
                    out_spk2[idx] = (mem - thre) > 0.f ? 1.f : 0.f;
                    out_b2[idx]   = bb;
                }
            }
        }
    }
}

// ---------------------------------------------------------------------------
// Head: pooling + mem_out update + log_softmax
// ---------------------------------------------------------------------------
__global__ void head_kernel(
    const float* __restrict__ spk2n, const float* __restrict__ mem_out,
    const float* __restrict__ out_tau_m,
    float* __restrict__ log_sm, float* __restrict__ mem_out_n)
{
    __shared__ float xo[NOUT];
    const int row = blockIdx.x;
    const int w = threadIdx.x >> 5, lane = threadIdx.x & 31;
    float s = 0.f;
    const float* p = spk2n + (size_t)row * NH1 + w * 200;
    for (int i = lane; i < 200; i += 32) s += p[i];
    #pragma unroll
    for (int o = 16; o > 0; o >>= 1) s += __shfl_down_sync(0xffffffffu, s, o);
    if (lane == 0) xo[w] = s;
    __syncthreads();
    if (threadIdx.x == 0) {
        float v[NOUT];
        float mx = -1e30f;
        #pragma unroll
        for (int o = 0; o < NOUT; o++) {
            const float m = mem_out[(size_t)row * NOUT + o];
            const float mo = m + (xo[o] - m) * sigm(out_tau_m[o]);
            v[o] = mo; mem_out_n[(size_t)row * NOUT + o] = mo;
            mx = fmaxf(mx, mo);
        }
        float se = 0.f;
        #pragma unroll
        for (int o = 0; o < NOUT; o++) se += expf(v[o] - mx);
        const float lse = mx + logf(se);
        #pragma unroll
        for (int o = 0; o < NOUT; o++) log_sm[(size_t)row * NOUT + o] = v[o] - lse;
    }
}

// ---------------------------------------------------------------------------
// Launch
// ---------------------------------------------------------------------------
extern "C" void kernel_launch(void* const* d_in, const int* in_sizes, int n_in,
                              void* d_out, int out_size)
{
    const float* x_t       = (const float*)d_in[0];
    const float* mem1      = (const float*)d_in[1];
    const float* spk1      = (const float*)d_in[2];
    const float* b1        = (const float*)d_in[3];
    const float* mem2      = (const float*)d_in[4];
    const float* spk2      = (const float*)d_in[5];
    const float* b2        = (const float*)d_in[6];
    const float* mem_out   = (const float*)d_in[7];
    const float* fc_w      = (const float*)d_in[8];
    const float* fc_b      = (const float*)d_in[9];
    const float* tau_adp1  = (const float*)d_in[10];
    const float* tau_m1    = (const float*)d_in[11];
    const float* x2in_w    = (const float*)d_in[12];
    const float* x2in_b    = (const float*)d_in[13];
    const float* rec4in_w  = (const float*)d_in[14];
    const float* rec4in_b  = (const float*)d_in[15];
    const float* in2out_w  = (const float*)d_in[16];
    const float* in2out_b  = (const float*)d_in[17];
    const float* rec4out_w = (const float*)d_in[18];
    const float* rec4out_b = (const float*)d_in[19];
    const float* out2in_w  = (const float*)d_in[20];
    const float* out2in_b  = (const float*)d_in[21];
    const float* tau_adp2  = (const float*)d_in[22];
    const float* tau_m2    = (const float*)d_in[23];
    const float* out_tau_m = (const float*)d_in[24];

    float* out = (float*)d_out;
    const size_t BH = (size_t)NB * NH0;
    float* log_sm    = out;
    float* mem1n     = out + (size_t)NB * NOUT;
    float* spk1n     = mem1n + BH;
    float* b1n       = spk1n + BH;
    float* mem2n     = b1n + BH;
    float* spk2n     = mem2n + BH;
    float* b2n       = spk2n + BH;
    float* mem_out_n = b2n + BH;

    cudaFuncSetAttribute(gemm1_h2_kernel, cudaFuncAttributeMaxDynamicSharedMemorySize,
                         SMEM_G1);
    cudaFuncSetAttribute(gemm2_h2_kernel, cudaFuncAttributeMaxDynamicSharedMemorySize,
                         SMEM_G2);

    {
        const long T = 4L * NR * NR + (long)NR * NH0 + (long)NH0 * IN_D
                     + (long)NB * IN_D + NH1 + NH0;
        convPre_kernel<<<(int)((T + 255) / 256), 256>>>(
            rec4out_w, in2out_w, out2in_w, rec4in_w, x2in_w, fc_w, x_t,
            tau_m1, tau_adp1, tau_m2, tau_adp2,
            rec4out_b, in2out_b, out2in_b, rec4in_b, x2in_b);
    }

    gemm1_h2_kernel<<<dim3(32, 32), 512, SMEM_G1>>>(
        fc_b, mem1, spk1, b1, mem1n, spk1n, b1n);

    {
        const long T = (long)NB * NH1;
        convA_kernel<<<(int)((T + 255) / 256), 256>>>(spk2);
    }

    gemm2_h2_kernel<<<dim3(32, 16, 2), 512, SMEM_G2>>>(
        spk2, mem2, b2, mem2n, spk2n, b2n);

    head_kernel<<<NB, 320>>>(spk2n, mem_out, out_tau_m, log_sm, mem_out_n);
}

// round 14
// speedup vs baseline: 1.2134x; 1.1158x over previous
#include <cuda_runtime.h>
#include <cuda_fp16.h>
#include <cstdint>

// Problem dims
#define NB    4096
#define IN_D  1024
#define NH0   4000
#define NH1   4000
#define NR    2000
#define NOUT  10
#define KP0   4096
#define KP1   8192
#define NPAD  2048
#define N1PAD 4096

#define BASE_THRE 0.1f
#define R_M       3.0f
#define BETA      1.8f

#define SC1   2.44140625e-4f   // 2^-12 fold scale

// ---------------------------------------------------------------------------
// Static device scratch (zero-initialized; pad regions stay zero forever)
// ---------------------------------------------------------------------------
__device__ __align__(256) __half g_Wo[2][(size_t)NPAD * KP0];
__device__ __align__(256) __half g_Wi[2][(size_t)NPAD * KP1];
__device__ __align__(256) __half g_Ah[(size_t)NB * KP1];
__device__ __align__(256) __half g_X[2][(size_t)NB * IN_D];
__device__ __align__(256) __half g_Wf[2][(size_t)N1PAD * IN_D];
__device__ float g_stm1[NH0];
__device__ float g_sta1[NH0];
__device__ float g_stm2[NH1];
__device__ float g_sta2[NH1];
__device__ float g_bias2[NH1];

__device__ __forceinline__ float sigm(float x) { return 1.0f / (1.0f + expf(-x)); }

__device__ __forceinline__ uint32_t smem_u32(const void* p) {
    uint32_t a;
    asm("{ .reg .u64 t; cvta.to.shared.u64 t, %1; cvt.u32.u64 %0, t; }" : "=r"(a) : "l"(p));
    return a;
}
__device__ __forceinline__ void cp16(uint32_t dst, const void* src) {
    asm volatile("cp.async.cg.shared.global [%0], [%1], 16;" :: "r"(dst), "l"(src) : "memory");
}
#define CP_COMMIT() asm volatile("cp.async.commit_group;" ::: "memory")
#define CP_WAIT1()  asm volatile("cp.async.wait_group 1;" ::: "memory")
#define CP_WAIT2()  asm volatile("cp.async.wait_group 2;" ::: "memory")

__device__ __forceinline__ void ldm_x4(uint32_t& r0, uint32_t& r1, uint32_t& r2, uint32_t& r3,
                                       uint32_t addr) {
    asm volatile("ldmatrix.sync.aligned.m8n8.x4.shared.b16 {%0,%1,%2,%3}, [%4];"
                 : "=r"(r0), "=r"(r1), "=r"(r2), "=r"(r3) : "r"(addr));
}
__device__ __forceinline__ void hmma16816(float* c, const uint32_t* a, uint32_t b0, uint32_t b1) {
    asm volatile(
        "mma.sync.aligned.m16n8k16.row.col.f32.f16.f16.f32 "
        "{%0,%1,%2,%3}, {%4,%5,%6,%7}, {%8,%9}, {%0,%1,%2,%3};"
        : "+f"(c[0]), "+f"(c[1]), "+f"(c[2]), "+f"(c[3])
        : "r"(a[0]), "r"(a[1]), "r"(a[2]), "r"(a[3]), "r"(b0), "r"(b1));
}

__device__ __forceinline__ void split2h(float w, __half& h0, __half& h1) {
    h0 = __float2half(w);
    float r = w - __half2float(h0);
    h1 = __float2half(r * 4096.0f);
}

// XOR-swizzled tile offset: 128 rows x 128B (8 chunks of 16B), conflict-free
__device__ __forceinline__ uint32_t sw(int row, int ch) {
    return (uint32_t)(row * 128 + ((ch ^ (row & 7)) << 4));
}

// ---------------------------------------------------------------------------
// convPre1: gemm1 dependencies only (fc_w split, x_t split, layer1 sigms)
// ---------------------------------------------------------------------------
__global__ void convPre1_kernel(
    const float* __restrict__ fc_w, const float* __restrict__ x_t,
    const float* __restrict__ tau_m1, const float* __restrict__ tau_adp1)
{
    const long SF = (long)NH0 * IN_D;
    const long SX = (long)NB * IN_D;
    long i = (long)blockIdx.x * blockDim.x + threadIdx.x;
    if (i < SF) {
        __half a, b; split2h(fc_w[i], a, b);
        g_Wf[0][i] = a; g_Wf[1][i] = b;
    } else if (i < SF + SX) {
        long r = i - SF;
        __half a, b; split2h(x_t[r], a, b);
        g_X[0][r] = a; g_X[1][r] = b;
    } else if (i < SF + SX + NH0) {
        int g = (int)(i - SF - SX);
        g_stm1[g] = sigm(tau_m1[g]);
        g_sta1[g] = sigm(tau_adp1[g]);
    }
}

// ---------------------------------------------------------------------------
// convPre2: gemm2 weights + layer2 column params (runs on side stream)
// ---------------------------------------------------------------------------
__global__ void convPre2_kernel(
    const float* __restrict__ rec4out, const float* __restrict__ in2out,
    const float* __restrict__ out2in,  const float* __restrict__ rec4in,
    const float* __restrict__ x2in,
    const float* __restrict__ tau_m2,  const float* __restrict__ tau_adp2,
    const float* __restrict__ rec4out_b, const float* __restrict__ in2out_b,
    const float* __restrict__ out2in_b,  const float* __restrict__ rec4in_b,
    const float* __restrict__ x2in_b)
{
    const long S1 = (long)NR * NR;
    const long S2 = (long)NR * NH0;
    long i = (long)blockIdx.x * blockDim.x + threadIdx.x;
    if (i < 4 * S1) {
        int sel = (int)(i / S1);
        long r  = i % S1;
        int n = (int)(r / NR), k = (int)(r % NR);
        float w; size_t dst; int which;
        if (sel == 0)      { w = rec4out[r]; dst = (size_t)n * KP0 + k;        which = 0; }
        else if (sel == 1) { w = in2out[r];  dst = (size_t)n * KP0 + 2048 + k; which = 0; }
        else if (sel == 2) { w = out2in[r];  dst = (size_t)n * KP1 + k;        which = 1; }
        else               { w = rec4in[r];  dst = (size_t)n * KP1 + 2048 + k; which = 1; }
        __half a, b; split2h(w, a, b);
        if (which == 0) { g_Wo[0][dst] = a; g_Wo[1][dst] = b; }
        else            { g_Wi[0][dst] = a; g_Wi[1][dst] = b; }
    } else if (i < 4 * S1 + S2) {
        long r = i - 4 * S1;
        int n = (int)(r / NH0), k = (int)(r % NH0);
        __half a, b; split2h(x2in[r], a, b);
        size_t dst = (size_t)n * KP1 + 4096 + k;
        g_Wi[0][dst] = a; g_Wi[1][dst] = b;
    } else if (i < 4 * S1 + S2 + NH1) {
        int g = (int)(i - 4 * S1 - S2);
        g_stm2[g] = sigm(tau_m2[g]);
        g_sta2[g] = sigm(tau_adp2[g]);
        g_bias2[g] = (g < NR) ? (rec4out_b[g] + in2out_b[g])
                              : (x2in_b[g - NR] + rec4in_b[g - NR] + out2in_b[g - NR]);
    }
}

// Pack spk2 into fp16 A (vectorized pairs): [spk_out|0][spk_in|0]
__global__ void convA_kernel(const float* __restrict__ spk2)
{
    const long T1 = (long)NB * (NH1 / 2);
    long i = (long)blockIdx.x * blockDim.x + threadIdx.x;
    if (i < T1) {
        int b = (int)(i / (NH1 / 2));
        int k = (int)(i % (NH1 / 2)) * 2;
        const float2 v = *(const float2*)(spk2 + (size_t)b * NH1 + k);
        size_t dst = (size_t)b * KP1 + (k < NR ? k : k + 48);
        *(__half2*)(g_Ah + dst) = __floats2half2_rn(v.x, v.y);
    }
}

#define TSZ 16384   // tile bytes: 128 rows x 128B (BK=64 fp16)

// ---------------------------------------------------------------------------
// GEMM1: HMMA cross-split (x0w0 -> acc0; x0w1+x1w0 -> accS)
// CTA 128x128, 512 thr (16 warps 4x4), BK=64, 3 stages, XOR swizzle.
// Vectorized float2 epilogue; also writes fp16 spikes into g_Ah.
// ---------------------------------------------------------------------------
#define STG1    (4 * TSZ)
#define SMEM_G1 (3 * STG1)

__global__ void __launch_bounds__(512, 1) gemm1_h2_kernel(
    const float* __restrict__ fc_b,
    const float* __restrict__ mem1, const float* __restrict__ spk1, const float* __restrict__ b1,
    float* __restrict__ out_mem1, float* __restrict__ out_spk1, float* __restrict__ out_b1)
{
    extern __shared__ char smem[];
    const uint32_t sb = smem_u32(smem);
    const int tid  = threadIdx.x;
    const int wid  = tid >> 5;
    const int lane = tid & 31;
    const int m0   = blockIdx.x * 128;
    const int n0   = blockIdx.y * 128;
    const int C    = IN_D / 64;     // 16 chunks

    const __half* src[4] = {
        &g_X[0][(size_t)m0 * IN_D], &g_X[1][(size_t)m0 * IN_D],
        &g_Wf[0][(size_t)n0 * IN_D], &g_Wf[1][(size_t)n0 * IN_D] };

    auto issue = [&](int c) {
        const uint32_t dst = sb + (c % 3) * STG1;
        const size_t ko = (size_t)c * 64;
        #pragma unroll
        for (int j = 0; j < 8; j++) {
            const int i = tid + j * 512;
            const int row = i >> 3, ch = i & 7;     // row 0..511
            const int q = row >> 7, r = row & 127;
            cp16(dst + q * TSZ + sw(r, ch),
                 src[q] + (size_t)r * IN_D + ko + ch * 8);
        }
        CP_COMMIT();
    };

    const int wm = wid >> 2;     // 0..3
    const int wn = wid & 3;      // 0..3
    const int lrow = lane & 15;
    const int lch  = lane >> 4;

    float acc0[2][4][4], accS[2][4][4];
    #pragma unroll
    for (int mi = 0; mi < 2; mi++)
        #pragma unroll
        for (int ni = 0; ni < 4; ni++)
            #pragma unroll
            for (int r = 0; r < 4; r++) { acc0[mi][ni][r] = 0.f; accS[mi][ni][r] = 0.f; }

    issue(0); issue(1);

    for (int c = 0; c < C; c++) {
        CP_WAIT1();
        __syncthreads();
        if (c + 2 < C) issue(c + 2);
        else CP_COMMIT();

        const uint32_t stb = sb + (c % 3) * STG1;
        #pragma unroll
        for (int ks = 0; ks < 4; ks++) {
            const int ch = 2 * ks + lch;
            uint32_t a0[2][4], a1[2][4];
            #pragma unroll
            for (int mi = 0; mi < 2; mi++) {
                const int row = wm * 32 + mi * 16 + lrow;
                ldm_x4(a0[mi][0], a0[mi][1], a0[mi][2], a0[mi][3], stb + sw(row, ch));
                ldm_x4(a1[mi][0], a1[mi][1], a1[mi][2], a1[mi][3], stb + TSZ + sw(row, ch));
            }
            uint32_t b0[4][2], b1r[4][2];
            #pragma unroll
            for (int nj = 0; nj < 2; nj++) {
                const int row = wn * 32 + nj * 16 + lrow;
                uint32_t r0, r1, r2, r3;
                ldm_x4(r0, r1, r2, r3, stb + 2 * TSZ + sw(row, ch));
                b0[nj * 2 + 0][0] = r0; b0[nj * 2 + 0][1] = r2;
                b0[nj * 2 + 1][0] = r1; b0[nj * 2 + 1][1] = r3;
                ldm_x4(r0, r1, r2, r3, stb + 3 * TSZ + sw(row, ch));
                b1r[nj * 2 + 0][0] = r0; b1r[nj * 2 + 0][1] = r2;
                b1r[nj * 2 + 1][0] = r1; b1r[nj * 2 + 1][1] = r3;
            }
            #pragma unroll
            for (int mi = 0; mi < 2; mi++)
                #pragma unroll
                for (int ni = 0; ni < 4; ni++) {
                    hmma16816(acc0[mi][ni], a0[mi], b0[ni][0], b0[ni][1]);
                    hmma16816(accS[mi][ni], a0[mi], b1r[ni][0], b1r[ni][1]);
                    hmma16816(accS[mi][ni], a1[mi], b0[ni][0], b0[ni][1]);
                }
        }
    }

    // Vectorized epilogue (pairs along n; NH0 even)
    const int erow = lane >> 2;
    const int ecol = (lane & 3) * 2;
    #pragma unroll
    for (int mi = 0; mi < 2; mi++) {
        #pragma unroll
        for (int r2i = 0; r2i < 2; r2i++) {
            const int m = m0 + wm * 32 + mi * 16 + erow + r2i * 8;
            const size_t rowo = (size_t)m * NH0;
            const size_t arow = (size_t)m * KP1 + 4096;
            #pragma unroll
            for (int ni = 0; ni < 4; ni++) {
                const int n = n0 + wn * 32 + ni * 8 + ecol;
                if (n >= NH0) continue;
                const float2 spv = *(const float2*)(spk1 + rowo + n);
                const float2 bv  = *(const float2*)(b1 + rowo + n);
                const float2 mv  = *(const float2*)(mem1 + rowo + n);
                const float2 fbv = *(const float2*)(fc_b + n);
                const float2 tmv = *(const float2*)(g_stm1 + n);
                const float2 tav = *(const float2*)(g_sta1 + n);

                const float inp0 = acc0[mi][ni][r2i * 2 + 0]
                                 + SC1 * accS[mi][ni][r2i * 2 + 0] + fbv.x;
                const float inp1 = acc0[mi][ni][r2i * 2 + 1]
                                 + SC1 * accS[mi][ni][r2i * 2 + 1] + fbv.y;
                const float bb0 = tav.x * bv.x + (1.f - tav.x) * spv.x;
                const float bb1 = tav.y * bv.y + (1.f - tav.y) * spv.y;
                const float th0 = BASE_THRE + BETA * bb0;
                const float th1 = BASE_THRE + BETA * bb1;
                const float me0 = mv.x * tmv.x + (1.f - tmv.x) * R_M * inp0 - th0 * spv.x;
                const float me1 = mv.y * tmv.y + (1.f - tmv.y) * R_M * inp1 - th1 * spv.y;
                const float sn0 = (me0 - th0) > 0.f ? 1.f : 0.f;
                const float sn1 = (me1 - th1) > 0.f ? 1.f : 0.f;

                *(float2*)(out_mem1 + rowo + n) = make_float2(me0, me1);
                *(float2*)(out_spk1 + rowo + n) = make_float2(sn0, sn1);
                *(float2*)(out_b1   + rowo + n) = make_float2(bb0, bb1);
                *(__half2*)(g_Ah + arow + n) = __floats2half2_rn(sn0, sn1);
            }
        }
    }
}

// ---------------------------------------------------------------------------
// GEMM2: HMMA 2-term weight split. CTA 128x128, 512 thr (16 warps 4x4),
// BK=64, 4 stages, XOR swizzle. Vectorized float2 epilogue.
// grid: (32 m, 16 n, 2 modes)
// ---------------------------------------------------------------------------
#define STG2    (3 * TSZ)
#define SMEM_G2 (4 * STG2)

__global__ void __launch_bounds__(512, 1) gemm2_h2_kernel(
    const float* __restrict__ spk2, const float* __restrict__ mem2,
    const float* __restrict__ b2,
    float* __restrict__ out_mem2, float* __restrict__ out_spk2, float* __restrict__ out_b2)
{
    extern __shared__ char smem[];
    const uint32_t sb = smem_u32(smem);
    const int tid  = threadIdx.x;
    const int wid  = tid >> 5;
    const int lane = tid & 31;
    const int mode = blockIdx.z;
    const int m0   = blockIdx.x * 128;
    const int n0   = blockIdx.y * 128;

    const int Kpad = mode ? KP1 : KP0;
    const int C    = Kpad / 64;
    const __half* A0 = g_Ah + (size_t)m0 * KP1;
    const __half* W0 = (mode ? &g_Wi[0][0] : &g_Wo[0][0]) + (size_t)n0 * Kpad;
    const __half* W1 = (mode ? &g_Wi[1][0] : &g_Wo[1][0]) + (size_t)n0 * Kpad;

    auto issue = [&](int c) {
        const uint32_t dst = sb + (c & 3) * STG2;
        const size_t ko = (size_t)c * 64;
        #pragma unroll
        for (int j = 0; j < 6; j++) {
            const int i = tid + j * 512;
            const int row = i >> 3, ch = i & 7;     // row 0..383
            const int q = row >> 7, r = row & 127;
            const __half* s = (q == 0) ? A0 : (q == 1 ? W0 : W1);
            const size_t stride = (q == 0) ? KP1 : Kpad;
            cp16(dst + q * TSZ + sw(r, ch), s + (size_t)r * stride + ko + ch * 8);
        }
        CP_COMMIT();
    };

    const int wm = wid >> 2;
    const int wn = wid & 3;
    const int lrow = lane & 15;
    const int lch  = lane >> 4;

    float acc0[2][4][4], acc1[2][4][4];
    #pragma unroll
    for (int mi = 0; mi < 2; mi++)
        #pragma unroll
        for (int ni = 0; ni < 4; ni++)
            #pragma unroll
            for (int r = 0; r < 4; r++) { acc0[mi][ni][r] = 0.f; acc1[mi][ni][r] = 0.f; }

    issue(0); issue(1); issue(2);

    for (int c = 0; c < C; c++) {
        CP_WAIT2();
        __syncthreads();
        if (c + 3 < C) issue(c + 3);
        else CP_COMMIT();

        const uint32_t stb = sb + (c & 3) * STG2;
        #pragma unroll
        for (int ks = 0; ks < 4; ks++) {
            const int ch = 2 * ks + lch;
            uint32_t a[2][4];
            #pragma unroll
            for (int mi = 0; mi < 2; mi++) {
                const int row = wm * 32 + mi * 16 + lrow;
                ldm_x4(a[mi][0], a[mi][1], a[mi][2], a[mi][3], stb + sw(row, ch));
            }
            #pragma unroll
            for (int t = 0; t < 2; t++) {
                uint32_t b[4][2];
                #pragma unroll
                for (int nj = 0; nj < 2; nj++) {
                    const int row = wn * 32 + nj * 16 + lrow;
                    uint32_t r0, r1, r2, r3;
                    ldm_x4(r0, r1, r2, r3, stb + (1 + t) * TSZ + sw(row, ch));
                    b[nj * 2 + 0][0] = r0; b[nj * 2 + 0][1] = r2;
                    b[nj * 2 + 1][0] = r1; b[nj * 2 + 1][1] = r3;
                }
                float (*acc)[4][4] = t ? acc1 : acc0;
                #pragma unroll
                for (int mi = 0; mi < 2; mi++)
                    #pragma unroll
                    for (int ni = 0; ni < 4; ni++)
                        hmma16816(acc[mi][ni], a[mi], b[ni][0], b[ni][1]);
            }
        }
    }

    // Vectorized epilogue (pairs along n; NR even)
    const int erow = lane >> 2;
    const int ecol = (lane & 3) * 2;
    #pragma unroll
    for (int mi = 0; mi < 2; mi++) {
        #pragma unroll
        for (int r2i = 0; r2i < 2; r2i++) {
            const int m = m0 + wm * 32 + mi * 16 + erow + r2i * 8;
            const size_t rowo = (size_t)m * NH1;
            #pragma unroll
            for (int ni = 0; ni < 4; ni++) {
                const int nl = n0 + wn * 32 + ni * 8 + ecol;
                if (nl >= NR) continue;
                const int g = mode * NR + nl;
                const size_t idx = rowo + g;
                const float2 spv = *(const float2*)(spk2 + idx);
                const float2 bv  = *(const float2*)(b2 + idx);
                const float2 mv  = *(const float2*)(mem2 + idx);
                const float2 biv = *(const float2*)(g_bias2 + g);
                const float2 tmv = *(const float2*)(g_stm2 + g);
                const float2 tav = *(const float2*)(g_sta2 + g);

                const float v0 = acc0[mi][ni][r2i * 2 + 0]
                               + SC1 * acc1[mi][ni][r2i * 2 + 0] + biv.x;
                const float v1 = acc0[mi][ni][r2i * 2 + 1]
                               + SC1 * acc1[mi][ni][r2i * 2 + 1] + biv.y;
                const float bb0 = tav.x * bv.x + (1.f - tav.x) * spv.x;
                const float bb1 = tav.y * bv.y + (1.f - tav.y) * spv.y;
                const float th0 = BASE_THRE + BETA * bb0;
                const float th1 = BASE_THRE + BETA * bb1;
                const float me0 = mv.x * tmv.x + (1.f - tmv.x) * R_M * v0 - th0 * spv.x;
                const float me1 = mv.y * tmv.y + (1.f - tmv.y) * R_M * v1 - th1 * spv.y;
                const float sn0 = (me0 - th0) > 0.f ? 1.f : 0.f;
                const float sn1 = (me1 - th1) > 0.f ? 1.f : 0.f;

                *(float2*)(out_mem2 + idx) = make_float2(me0, me1);
                *(float2*)(out_spk2 + idx) = make_float2(sn0, sn1);
                *(float2*)(out_b2   + idx) = make_float2(bb0, bb1);
            }
        }
    }
}

// ---------------------------------------------------------------------------
// Head: pooling + mem_out update + log_softmax
// ---------------------------------------------------------------------------
__global__ void head_kernel(
    const float* __restrict__ spk2n, const float* __restrict__ mem_out,
    const float* __restrict__ out_tau_m,
    float* __restrict__ log_sm, float* __restrict__ mem_out_n)
{
    __shared__ float xo[NOUT];
    const int row = blockIdx.x;
    const int w = threadIdx.x >> 5, lane = threadIdx.x & 31;
    float s = 0.f;
    const float* p = spk2n + (size_t)row * NH1 + w * 200;
    for (int i = lane; i < 200; i += 32) s += p[i];
    #pragma unroll
    for (int o = 16; o > 0; o >>= 1) s += __shfl_down_sync(0xffffffffu, s, o);
    if (lane == 0) xo[w] = s;
    __syncthreads();
    if (threadIdx.x == 0) {
        float v[NOUT];
        float mx = -1e30f;
        #pragma unroll
        for (int o = 0; o < NOUT; o++) {
            const float m = mem_out[(size_t)row * NOUT + o];
            const float mo = m + (xo[o] - m) * sigm(out_tau_m[o]);
            v[o] = mo; mem_out_n[(size_t)row * NOUT + o] = mo;
            mx = fmaxf(mx, mo);
        }
        float se = 0.f;
        #pragma unroll
        for (int o = 0; o < NOUT; o++) se += expf(v[o] - mx);
        const float lse = mx + logf(se);
        #pragma unroll
        for (int o = 0; o < NOUT; o++) log_sm[(size_t)row * NOUT + o] = v[o] - lse;
    }
}

// ---------------------------------------------------------------------------
// Launch (fork/join: side stream runs gemm2-only conversions under gemm1)
// ---------------------------------------------------------------------------
static cudaStream_t g_s2 = nullptr;
static cudaEvent_t  g_evFork = nullptr, g_evJoin = nullptr;

extern "C" void kernel_launch(void* const* d_in, const int* in_sizes, int n_in,
                              void* d_out, int out_size)
{
    const float* x_t       = (const float*)d_in[0];
    const float* mem1      = (const float*)d_in[1];
    const float* spk1      = (const float*)d_in[2];
    const float* b1        = (const float*)d_in[3];
    const float* mem2      = (const float*)d_in[4];
    const float* spk2      = (const float*)d_in[5];
    const float* b2        = (const float*)d_in[6];
    const float* mem_out   = (const float*)d_in[7];
    const float* fc_w      = (const float*)d_in[8];
    const float* fc_b      = (const float*)d_in[9];
    const float* tau_adp1  = (const float*)d_in[10];
    const float* tau_m1    = (const float*)d_in[11];
    const float* x2in_w    = (const float*)d_in[12];
    const float* x2in_b    = (const float*)d_in[13];
    const float* rec4in_w  = (const float*)d_in[14];
    const float* rec4in_b  = (const float*)d_in[15];
    const float* in2out_w  = (const float*)d_in[16];
    const float* in2out_b  = (const float*)d_in[17];
    const float* rec4out_w = (const float*)d_in[18];
    const float* rec4out_b = (const float*)d_in[19];
    const float* out2in_w  = (const float*)d_in[20];
    const float* out2in_b  = (const float*)d_in[21];
    const float* tau_adp2  = (const float*)d_in[22];
    const float* tau_m2    = (const float*)d_in[23];
    const float* out_tau_m = (const float*)d_in[24];

    float* out = (float*)d_out;
    const size_t BH = (size_t)NB * NH0;
    float* log_sm    = out;
    float* mem1n     = out + (size_t)NB * NOUT;
    float* spk1n     = mem1n + BH;
    float* b1n       = spk1n + BH;
    float* mem2n     = b1n + BH;
    float* spk2n     = mem2n + BH;
    float* b2n       = spk2n + BH;
    float* mem_out_n = b2n + BH;

    if (g_s2 == nullptr) {
        cudaStreamCreateWithFlags(&g_s2, cudaStreamNonBlocking);
        cudaEventCreateWithFlags(&g_evFork, cudaEventDisableTiming);
        cudaEventCreateWithFlags(&g_evJoin, cudaEventDisableTiming);
    }

    cudaFuncSetAttribute(gemm1_h2_kernel, cudaFuncAttributeMaxDynamicSharedMemorySize,
                         SMEM_G1);
    cudaFuncSetAttribute(gemm2_h2_kernel, cudaFuncAttributeMaxDynamicSharedMemorySize,
                         SMEM_G2);

    // Fork: side stream handles gemm2-only conversions (DRAM-bound) so they
    // overlap with gemm1 (smem-bound).
    cudaEventRecord(g_evFork, 0);
    cudaStreamWaitEvent(g_s2, g_evFork, 0);
    {
        const long T = 4L * NR * NR + (long)NR * NH0 + NH1;
        convPre2_kernel<<<(int)((T + 255) / 256), 256, 0, g_s2>>>(
            rec4out_w, in2out_w, out2in_w, rec4in_w, x2in_w,
            tau_m2, tau_adp2, rec4out_b, in2out_b, out2in_b, rec4in_b, x2in_b);
    }
    {
        const long T = (long)NB * (NH1 / 2);
        convA_kernel<<<(int)((T + 255) / 256), 256, 0, g_s2>>>(spk2);
    }
    cudaEventRecord(g_evJoin, g_s2);

    // Main stream: gemm1 deps, then gemm1.
    {
        const long T = (long)NH0 * IN_D + (long)NB * IN_D + NH0;
        convPre1_kernel<<<(int)((T + 255) / 256), 256>>>(fc_w, x_t, tau_m1, tau_adp1);
    }
    gemm1_h2_kernel<<<dim3(32, 32), 512, SMEM_G1>>>(
        fc_b, mem1, spk1, b1, mem1n, spk1n, b1n);

    // Join before gemm2 (needs W planes + spk2-half of g_Ah).
    cudaStreamWaitEvent(0, g_evJoin, 0);

    gemm2_h2_kernel<<<dim3(32, 16, 2), 512, SMEM_G2>>>(
        spk2, mem2, b2, mem2n, spk2n, b2n);

    head_kernel<<<NB, 320>>>(spk2n, mem_out, out_tau_m, log_sm, mem_out_n);
}

// round 17
// speedup vs baseline: 1.2686x; 1.0455x over previous
#include <cuda_runtime.h>
#include <cuda_fp16.h>
#include <cstdint>

// Problem dims
#define NB    4096
#define IN_D  1024
#define NH0   4000
#define NH1   4000
#define NR    2000
#define NOUT  10
#define KP0   4096
#define KP1   8192
#define NPAD  2048
#define N1PAD 4096

#define BASE_THRE 0.1f
#define R_M       3.0f
#define BETA      1.8f

#define SC1   2.44140625e-4f   // 2^-12 fold scale

// ---------------------------------------------------------------------------
// Static device scratch — ALL gemm operands stored as pre-swizzled 16KB tile
// blocks: [tile][chunk] blocks of 128 rows x 64 halves (XOR swizzle baked in).
// ---------------------------------------------------------------------------
__device__ __align__(256) __half g_Wo[2][(size_t)NPAD * KP0];   // 16 ntile x 64 chunk
__device__ __align__(256) __half g_Wi[2][(size_t)NPAD * KP1];   // 16 ntile x 128 chunk
__device__ __align__(256) __half g_Ah[(size_t)NB * KP1];        // 32 mtile x 128 chunk
__device__ __align__(256) __half g_X[2][(size_t)NB * IN_D];     // 32 mtile x 16 chunk
__device__ __align__(256) __half g_Wf[2][(size_t)N1PAD * IN_D]; // 32 ntile x 16 chunk
__device__ float g_stm1[NH0];
__device__ float g_sta1[NH0];
__device__ float g_stm2[NH1];
__device__ float g_sta2[NH1];
__device__ float g_bias2[NH1];

__device__ __forceinline__ float sigm(float x) { return 1.0f / (1.0f + expf(-x)); }

__device__ __forceinline__ uint32_t smem_u32(const void* p) {
    uint32_t a;
    asm("{ .reg .u64 t; cvta.to.shared.u64 t, %1; cvt.u32.u64 %0, t; }" : "=r"(a) : "l"(p));
    return a;
}

// XOR-swizzled offset within a 16KB tile block (128 rows x 128B)
__device__ __forceinline__ uint32_t sw(int row, int ch) {
    return (uint32_t)(row * 128 + ((ch ^ (row & 7)) << 4));
}
// byte offset of element (r, kk) inside tiled array at block index
__device__ __forceinline__ size_t tblk(int block, int r, int kk) {
    return (size_t)block * 16384 + sw(r, kk >> 3) + ((kk & 7) << 1);
}

// ---- TMA bulk + mbarrier -------------------------------------------------
__device__ __forceinline__ void tma_bulk(uint32_t dst, const void* src, uint32_t bytes,
                                         uint32_t mbar) {
    asm volatile(
        "cp.async.bulk.shared::cluster.global.mbarrier::complete_tx::bytes "
        "[%0], [%1], %2, [%3];"
        :: "r"(dst), "l"(src), "r"(bytes), "r"(mbar) : "memory");
}
#define MBAR_INIT(addr, cnt) \
    asm volatile("mbarrier.init.shared.b64 [%0], %1;" :: "r"(addr), "r"(cnt) : "memory")
#define MBAR_EXPECT(addr, tx) \
    asm volatile("mbarrier.arrive.expect_tx.shared.b64 _, [%0], %1;" \
                 :: "r"(addr), "r"((uint32_t)(tx)) : "memory")
#define MBAR_WAIT(addr, par) do {                                                        \
    uint32_t _m = (addr), _p = (par), _d;                                                \
    asm volatile("{ .reg .pred p; mbarrier.try_wait.parity.acquire.cta.shared::cta.b64 " \
                 "p, [%1], %2; selp.b32 %0, 1, 0, p; }"                                  \
                 : "=r"(_d) : "r"(_m), "r"(_p) : "memory");                              \
    if (!_d) {                                                                           \
        asm volatile("{ .reg .pred P1; WL_%=: mbarrier.try_wait.parity.acquire.cta."     \
                     "shared::cta.b64 P1, [%0], %1, 0x989680; @P1 bra.uni WD_%=; "       \
                     "bra.uni WL_%=; WD_%=: }" :: "r"(_m), "r"(_p) : "memory");          \
    }                                                                                    \
} while (0)

__device__ __forceinline__ void ldm_x4(uint32_t& r0, uint32_t& r1, uint32_t& r2, uint32_t& r3,
                                       uint32_t addr) {
    asm volatile("ldmatrix.sync.aligned.m8n8.x4.shared.b16 {%0,%1,%2,%3}, [%4];"
                 : "=r"(r0), "=r"(r1), "=r"(r2), "=r"(r3) : "r"(addr));
}
__device__ __forceinline__ void hmma16816(float* c, const uint32_t* a, uint32_t b0, uint32_t b1) {
    asm volatile(
        "mma.sync.aligned.m16n8k16.row.col.f32.f16.f16.f32 "
        "{%0,%1,%2,%3}, {%4,%5,%6,%7}, {%8,%9}, {%0,%1,%2,%3};"
        : "+f"(c[0]), "+f"(c[1]), "+f"(c[2]), "+f"(c[3])
        : "r"(a[0]), "r"(a[1]), "r"(a[2]), "r"(a[3]), "r"(b0), "r"(b1));
}

__device__ __forceinline__ void split2h(float w, __half& h0, __half& h1) {
    h0 = __float2half(w);
    float r = w - __half2float(h0);
    h1 = __float2half(r * 4096.0f);
}

// ---------------------------------------------------------------------------
// convPre1: gemm1 deps — fc_w / x_t splits into tiled blocks + layer1 sigms
// ---------------------------------------------------------------------------
__global__ void convPre1_kernel(
    const float* __restrict__ fc_w, const float* __restrict__ x_t,
    const float* __restrict__ tau_m1, const float* __restrict__ tau_adp1)
{
    const long SF = (long)NH0 * IN_D;
    const long SX = (long)NB * IN_D;
    long i = (long)blockIdx.x * blockDim.x + threadIdx.x;
    if (i < SF) {
        int n = (int)(i / IN_D), k = (int)(i % IN_D);
        __half a, b; split2h(fc_w[i], a, b);
        const size_t off = tblk((n >> 7) * 16 + (k >> 6), n & 127, k & 63);
        *(__half*)((char*)g_Wf[0] + off) = a;
        *(__half*)((char*)g_Wf[1] + off) = b;
    } else if (i < SF + SX) {
        long r = i - SF;
        int m = (int)(r / IN_D), k = (int)(r % IN_D);
        __half a, b; split2h(x_t[r], a, b);
        const size_t off = tblk((m >> 7) * 16 + (k >> 6), m & 127, k & 63);
        *(__half*)((char*)g_X[0] + off) = a;
        *(__half*)((char*)g_X[1] + off) = b;
    } else if (i < SF + SX + NH0) {
        int g = (int)(i - SF - SX);
        g_stm1[g] = sigm(tau_m1[g]);
        g_sta1[g] = sigm(tau_adp1[g]);
    }
}

// ---------------------------------------------------------------------------
// convPre2: gemm2 weights into tiled blocks + layer2 column params
// ---------------------------------------------------------------------------
__global__ void convPre2_kernel(
    const float* __restrict__ rec4out, const float* __restrict__ in2out,
    const float* __restrict__ out2in,  const float* __restrict__ rec4in,
    const float* __restrict__ x2in,
    const float* __restrict__ tau_m2,  const float* __restrict__ tau_adp2,
    const float* __restrict__ rec4out_b, const float* __restrict__ in2out_b,
    const float* __restrict__ out2in_b,  const float* __restrict__ rec4in_b,
    const float* __restrict__ x2in_b)
{
    const long S1 = (long)NR * NR;
    const long S2 = (long)NR * NH0;
    long i = (long)blockIdx.x * blockDim.x + threadIdx.x;
    if (i < 4 * S1) {
        int sel = (int)(i / S1);
        long r  = i % S1;
        int n = (int)(r / NR), k = (int)(r % NR);
        float w; int key, which;
        if (sel == 0)      { w = rec4out[r]; key = k;        which = 0; }
        else if (sel == 1) { w = in2out[r];  key = k + 2048; which = 0; }
        else if (sel == 2) { w = out2in[r];  key = k;        which = 1; }
        else               { w = rec4in[r];  key = k + 2048; which = 1; }
        __half a, b; split2h(w, a, b);
        const int C = which ? 128 : 64;
        const size_t off = tblk((n >> 7) * C + (key >> 6), n & 127, key & 63);
        if (which == 0) {
            *(__half*)((char*)g_Wo[0] + off) = a;
            *(__half*)((char*)g_Wo[1] + off) = b;
        } else {
            *(__half*)((char*)g_Wi[0] + off) = a;
            *(__half*)((char*)g_Wi[1] + off) = b;
        }
    } else if (i < 4 * S1 + S2) {
        long r = i - 4 * S1;
        int n = (int)(r / NH0), k = (int)(r % NH0);
        __half a, b; split2h(x2in[r], a, b);
        const int key = k + 4096;
        const size_t off = tblk((n >> 7) * 128 + (key >> 6), n & 127, key & 63);
        *(__half*)((char*)g_Wi[0] + off) = a;
        *(__half*)((char*)g_Wi[1] + off) = b;
    } else if (i < 4 * S1 + S2 + NH1) {
        int g = (int)(i - 4 * S1 - S2);
        g_stm2[g] = sigm(tau_m2[g]);
        g_sta2[g] = sigm(tau_adp2[g]);
        g_bias2[g] = (g < NR) ? (rec4out_b[g] + in2out_b[g])
                              : (x2in_b[g - NR] + rec4in_b[g - NR] + out2in_b[g - NR]);
    }
}

// Pack spk2 into tiled g_Ah blocks (pairs)
__global__ void convA_kernel(const float* __restrict__ spk2)
{
    const long T1 = (long)NB * (NH1 / 2);
    long i = (long)blockIdx.x * blockDim.x + threadIdx.x;
    if (i < T1) {
        int b = (int)(i / (NH1 / 2));
        int k = (int)(i % (NH1 / 2)) * 2;
        const float2 v = *(const float2*)(spk2 + (size_t)b * NH1 + k);
        const int kp = (k < NR) ? k : k + 48;
        const size_t off = tblk((b >> 7) * 128 + (kp >> 6), b & 127, kp & 63);
        *(__half2*)((char*)g_Ah + off) = __floats2half2_rn(v.x, v.y);
    }
}

#define TSZ 16384   // tile bytes: 128 rows x 128B (BK=64 fp16)

// ---------------------------------------------------------------------------
// GEMM1: HMMA cross-split. CTA 128x128, 512 thr (16 warps 4x4), BK=64,
// 3 TMA stages (X0,X1,W0,W1 = 64KB each). mbarrier-paced.
// ---------------------------------------------------------------------------
#define STG1    (4 * TSZ)
#define SMEM_G1 (3 * STG1 + 64)

__global__ void __launch_bounds__(512, 1) gemm1_h2_kernel(
    const float* __restrict__ fc_b,
    const float* __restrict__ mem1, const float* __restrict__ spk1, const float* __restrict__ b1,
    float* __restrict__ out_mem1, float* __restrict__ out_spk1, float* __restrict__ out_b1)
{
    extern __shared__ char smem[];
    const uint32_t sb = smem_u32(smem);
    const uint32_t mbb = sb + 3 * STG1;
    const int tid  = threadIdx.x;
    const int wid  = tid >> 5;
    const int lane = tid & 31;
    const int m0   = blockIdx.x * 128;
    const int n0   = blockIdx.y * 128;
    const int C    = IN_D / 64;     // 16 chunks
    const int mt   = m0 >> 7, nt = n0 >> 7;

    if (tid == 0) {
        MBAR_INIT(mbb + 0, 1); MBAR_INIT(mbb + 8, 1); MBAR_INIT(mbb + 16, 1);
    }
    __syncthreads();

    auto fill = [&](int c) {
        const int s = c % 3;
        const uint32_t mb = mbb + s * 8;
        const uint32_t d = sb + s * STG1;
        MBAR_EXPECT(mb, 4 * TSZ);
        tma_bulk(d,            (const char*)g_X[0]  + (size_t)(mt * 16 + c) * TSZ, TSZ, mb);
        tma_bulk(d + TSZ,      (const char*)g_X[1]  + (size_t)(mt * 16 + c) * TSZ, TSZ, mb);
        tma_bulk(d + 2 * TSZ,  (const char*)g_Wf[0] + (size_t)(nt * 16 + c) * TSZ, TSZ, mb);
        tma_bulk(d + 3 * TSZ,  (const char*)g_Wf[1] + (size_t)(nt * 16 + c) * TSZ, TSZ, mb);
    };
    if (tid == 0) { fill(0); fill(1); fill(2); }

    const int wm = wid >> 2;     // 0..3
    const int wn = wid & 3;      // 0..3
    const int lrow = lane & 15;
    const int lch  = lane >> 4;

    float acc0[2][4][4], accS[2][4][4];
    #pragma unroll
    for (int mi = 0; mi < 2; mi++)
        #pragma unroll
        for (int ni = 0; ni < 4; ni++)
            #pragma unroll
            for (int r = 0; r < 4; r++) { acc0[mi][ni][r] = 0.f; accS[mi][ni][r] = 0.f; }

    for (int c = 0; c < C; c++) {
        const int s = c % 3;
        MBAR_WAIT(mbb + s * 8, (c / 3) & 1);

        const uint32_t stb = sb + s * STG1;
        #pragma unroll
        for (int ks = 0; ks < 4; ks++) {
            const int ch = 2 * ks + lch;
            uint32_t a0[2][4], a1[2][4];
            #pragma unroll
            for (int mi = 0; mi < 2; mi++) {
                const int row = wm * 32 + mi * 16 + lrow;
                ldm_x4(a0[mi][0], a0[mi][1], a0[mi][2], a0[mi][3], stb + sw(row, ch));
                ldm_x4(a1[mi][0], a1[mi][1], a1[mi][2], a1[mi][3], stb + TSZ + sw(row, ch));
            }
            uint32_t b0[4][2], b1r[4][2];
            #pragma unroll
            for (int nj = 0; nj < 2; nj++) {
                const int row = wn * 32 + nj * 16 + lrow;
                uint32_t r0, r1, r2, r3;
                ldm_x4(r0, r1, r2, r3, stb + 2 * TSZ + sw(row, ch));
                b0[nj * 2 + 0][0] = r0; b0[nj * 2 + 0][1] = r2;
                b0[nj * 2 + 1][0] = r1; b0[nj * 2 + 1][1] = r3;
                ldm_x4(r0, r1, r2, r3, stb + 3 * TSZ + sw(row, ch));
                b1r[nj * 2 + 0][0] = r0; b1r[nj * 2 + 0][1] = r2;
                b1r[nj * 2 + 1][0] = r1; b1r[nj * 2 + 1][1] = r3;
            }
            #pragma unroll
            for (int mi = 0; mi < 2; mi++)
                #pragma unroll
                for (int ni = 0; ni < 4; ni++) {
                    hmma16816(acc0[mi][ni], a0[mi], b0[ni][0], b0[ni][1]);
                    hmma16816(accS[mi][ni], a0[mi], b1r[ni][0], b1r[ni][1]);
                    hmma16816(accS[mi][ni], a1[mi], b0[ni][0], b0[ni][1]);
                }
        }
        __syncthreads();
        if (tid == 0 && c + 3 < C) fill(c + 3);
    }

    // Vectorized epilogue (pairs along n; also writes fp16 spikes into tiled g_Ah)
    const int erow = lane >> 2;
    const int ecol = (lane & 3) * 2;
    #pragma unroll
    for (int mi = 0; mi < 2; mi++) {
        #pragma unroll
        for (int r2i = 0; r2i < 2; r2i++) {
            const int m = m0 + wm * 32 + mi * 16 + erow + r2i * 8;
            const size_t rowo = (size_t)m * NH0;
            #pragma unroll
            for (int ni = 0; ni < 4; ni++) {
                const int n = n0 + wn * 32 + ni * 8 + ecol;
                if (n >= NH0) continue;
                const float2 spv = *(const float2*)(spk1 + rowo + n);
                const float2 bv  = *(const float2*)(b1 + rowo + n);
                const float2 mv  = *(const float2*)(mem1 + rowo + n);
                const float2 fbv = *(const float2*)(fc_b + n);
                const float2 tmv = *(const float2*)(g_stm1 + n);
                const float2 tav = *(const float2*)(g_sta1 + n);

                const float inp0 = acc0[mi][ni][r2i * 2 + 0]
                                 + SC1 * accS[mi][ni][r2i * 2 + 0] + fbv.x;
                const float inp1 = acc0[mi][ni][r2i * 2 + 1]
                                 + SC1 * accS[mi][ni][r2i * 2 + 1] + fbv.y;
                const float bb0 = tav.x * bv.x + (1.f - tav.x) * spv.x;
                const float bb1 = tav.y * bv.y + (1.f - tav.y) * spv.y;
                const float th0 = BASE_THRE + BETA * bb0;
                const float th1 = BASE_THRE + BETA * bb1;
                const float me0 = mv.x * tmv.x + (1.f - tmv.x) * R_M * inp0 - th0 * spv.x;
                const float me1 = mv.y * tmv.y + (1.f - tmv.y) * R_M * inp1 - th1 * spv.y;
                const float sn0 = (me0 - th0) > 0.f ? 1.f : 0.f;
                const float sn1 = (me1 - th1) > 0.f ? 1.f : 0.f;

                *(float2*)(out_mem1 + rowo + n) = make_float2(me0, me1);
                *(float2*)(out_spk1 + rowo + n) = make_float2(sn0, sn1);
                *(float2*)(out_b1   + rowo + n) = make_float2(bb0, bb1);
                const int key = 4096 + n;
                const size_t aoff = tblk((m >> 7) * 128 + (key >> 6), m & 127, key & 63);
                *(__half2*)((char*)g_Ah + aoff) = __floats2half2_rn(sn0, sn1);
            }
        }
    }
}

// ---------------------------------------------------------------------------
// GEMM2: HMMA 2-term weight split. CTA 128x128, 512 thr, BK=64, 4 TMA stages
// (A,W0,W1 = 48KB each). grid: (32 m, 16 n, 2 modes). mbarrier-paced.
// ---------------------------------------------------------------------------
#define STG2    (3 * TSZ)
#define SMEM_G2 (4 * STG2 + 64)

__global__ void __launch_bounds__(512, 1) gemm2_h2_kernel(
    const float* __restrict__ spk2, const float* __restrict__ mem2,
    const float* __restrict__ b2,
    float* __restrict__ out_mem2, float* __restrict__ out_spk2, float* __restrict__ out_b2)
{
    extern __shared__ char smem[];
    const uint32_t sb = smem_u32(smem);
    const uint32_t mbb = sb + 4 * STG2;
    const int tid  = threadIdx.x;
    const int wid  = tid >> 5;
    const int lane = tid & 31;
    const int mode = blockIdx.z;
    const int m0   = blockIdx.x * 128;
    const int n0   = blockIdx.y * 128;

    const int C  = mode ? 128 : 64;
    const int mt = m0 >> 7, nt = n0 >> 7;
    const char* W0 = (const char*)(mode ? g_Wi[0] : g_Wo[0]);
    const char* W1 = (const char*)(mode ? g_Wi[1] : g_Wo[1]);

    if (tid == 0) {
        MBAR_INIT(mbb + 0, 1); MBAR_INIT(mbb + 8, 1);
        MBAR_INIT(mbb + 16, 1); MBAR_INIT(mbb + 24, 1);
    }
    __syncthreads();

    auto fill = [&](int c) {
        const int s = c & 3;
        const uint32_t mb = mbb + s * 8;
        const uint32_t d = sb + s * STG2;
        MBAR_EXPECT(mb, 3 * TSZ);
        tma_bulk(d,           (const char*)g_Ah + (size_t)(mt * 128 + c) * TSZ, TSZ, mb);
        tma_bulk(d + TSZ,     W0 + (size_t)(nt * C + c) * TSZ, TSZ, mb);
        tma_bulk(d + 2 * TSZ, W1 + (size_t)(nt * C + c) * TSZ, TSZ, mb);
    };
    if (tid == 0) { fill(0); fill(1); fill(2); }

    const int wm = wid >> 2;
    const int wn = wid & 3;
    const int lrow = lane & 15;
    const int lch  = lane >> 4;

    float acc0[2][4][4], acc1[2][4][4];
    #pragma unroll
    for (int mi = 0; mi < 2; mi++)
        #pragma unroll
        for (int ni = 0; ni < 4; ni++)
            #pragma unroll
            for (int r = 0; r < 4; r++) { acc0[mi][ni][r] = 0.f; acc1[mi][ni][r] = 0.f; }

    for (int c = 0; c < C; c++) {
        const int s = c & 3;
        MBAR_WAIT(mbb + s * 8, (c >> 2) & 1);

        const uint32_t stb = sb + s * STG2;
        #pragma unroll
        for (int ks = 0; ks < 4; ks++) {
            const int ch = 2 * ks + lch;
            uint32_t a[2][4];
            #pragma unroll
            for (int mi = 0; mi < 2; mi++) {
                const int row = wm * 32 + mi * 16 + lrow;
                ldm_x4(a[mi][0], a[mi][1], a[mi][2], a[mi][3], stb + sw(row, ch));
            }
            #pragma unroll
            for (int t = 0; t < 2; t++) {
                uint32_t b[4][2];
                #pragma unroll
                for (int nj = 0; nj < 2; nj++) {
                    const int row = wn * 32 + nj * 16 + lrow;
                    uint32_t r0, r1, r2, r3;
                    ldm_x4(r0, r1, r2, r3, stb + (1 + t) * TSZ + sw(row, ch));
                    b[nj * 2 + 0][0] = r0; b[nj * 2 + 0][1] = r2;
                    b[nj * 2 + 1][0] = r1; b[nj * 2 + 1][1] = r3;
                }
                float (*acc)[4][4] = t ? acc1 : acc0;
                #pragma unroll
                for (int mi = 0; mi < 2; mi++)
                    #pragma unroll
                    for (int ni = 0; ni < 4; ni++)
                        hmma16816(acc[mi][ni], a[mi], b[ni][0], b[ni][1]);
            }
        }
        __syncthreads();
        if (tid == 0 && c + 3 < C) fill(c + 3);
    }

    // Vectorized epilogue (pairs along n)
    const int erow = lane >> 2;
    const int ecol = (lane & 3) * 2;
    #pragma unroll
    for (int mi = 0; mi < 2; mi++) {
        #pragma unroll
        for (int r2i = 0; r2i < 2; r2i++) {
            const int m = m0 + wm * 32 + mi * 16 + erow + r2i * 8;
            const size_t rowo = (size_t)m * NH1;
            #pragma unroll
            for (int ni = 0; ni < 4; ni++) {
                const int nl = n0 + wn * 32 + ni * 8 + ecol;
                if (nl >= NR) continue;
                const int g = mode * NR + nl;
                const size_t idx = rowo + g;
                const float2 spv = *(const float2*)(spk2 + idx);
                const float2 bv  = *(const float2*)(b2 + idx);
                const float2 mv  = *(const float2*)(mem2 + idx);
                const float2 biv = *(const float2*)(g_bias2 + g);
                const float2 tmv = *(const float2*)(g_stm2 + g);
                const float2 tav = *(const float2*)(g_sta2 + g);

                const float v0 = acc0[mi][ni][r2i * 2 + 0]
                               + SC1 * acc1[mi][ni][r2i * 2 + 0] + biv.x;
                const float v1 = acc0[mi][ni][r2i * 2 + 1]
                               + SC1 * acc1[mi][ni][r2i * 2 + 1] + biv.y;
                const float bb0 = tav.x * bv.x + (1.f - tav.x) * spv.x;
                const float bb1 = tav.y * bv.y + (1.f - tav.y) * spv.y;
                const float th0 = BASE_THRE + BETA * bb0;
                const float th1 = BASE_THRE + BETA * bb1;
                const float me0 = mv.x * tmv.x + (1.f - tmv.x) * R_M * v0 - th0 * spv.x;
                const float me1 = mv.y * tmv.y + (1.f - tmv.y) * R_M * v1 - th1 * spv.y;
                const float sn0 = (me0 - th0) > 0.f ? 1.f : 0.f;
                const float sn1 = (me1 - th1) > 0.f ? 1.f : 0.f;

                *(float2*)(out_mem2 + idx) = make_float2(me0, me1);
                *(float2*)(out_spk2 + idx) = make_float2(sn0, sn1);
                *(float2*)(out_b2   + idx) = make_float2(bb0, bb1);
            }
        }
    }
}

// ---------------------------------------------------------------------------
// Head: pooling + mem_out update + log_softmax
// ---------------------------------------------------------------------------
__global__ void head_kernel(
    const float* __restrict__ spk2n, const float* __restrict__ mem_out,
    const float* __restrict__ out_tau_m,
    float* __restrict__ log_sm, float* __restrict__ mem_out_n)
{
    __shared__ float xo[NOUT];
    const int row = blockIdx.x;
    const int w = threadIdx.x >> 5, lane = threadIdx.x & 31;
    float s = 0.f;
    const float* p = spk2n + (size_t)row * NH1 + w * 200;
    for (int i = lane; i < 200; i += 32) s += p[i];
    #pragma unroll
    for (int o = 16; o > 0; o >>= 1) s += __shfl_down_sync(0xffffffffu, s, o);
    if (lane == 0) xo[w] = s;
    __syncthreads();
    if (threadIdx.x == 0) {
        float v[NOUT];
        float mx = -1e30f;
        #pragma unroll
        for (int o = 0; o < NOUT; o++) {
            const float m = mem_out[(size_t)row * NOUT + o];
            const float mo = m + (xo[o] - m) * sigm(out_tau_m[o]);
            v[o] = mo; mem_out_n[(size_t)row * NOUT + o] = mo;
            mx = fmaxf(mx, mo);
        }
        float se = 0.f;
        #pragma unroll
        for (int o = 0; o < NOUT; o++) se += expf(v[o] - mx);
        const float lse = mx + logf(se);
        #pragma unroll
        for (int o = 0; o < NOUT; o++) log_sm[(size_t)row * NOUT + o] = v[o] - lse;
    }
}

// ---------------------------------------------------------------------------
// Launch (fork/join: side stream runs gemm2-only conversions under gemm1)
// ---------------------------------------------------------------------------
static cudaStream_t g_s2 = nullptr;
static cudaEvent_t  g_evFork = nullptr, g_evJoin = nullptr;

extern "C" void kernel_launch(void* const* d_in, const int* in_sizes, int n_in,
                              void* d_out, int out_size)
{
    const float* x_t       = (const float*)d_in[0];
    const float* mem1      = (const float*)d_in[1];
    const float* spk1      = (const float*)d_in[2];
    const float* b1        = (const float*)d_in[3];
    const float* mem2      = (const float*)d_in[4];
    const float* spk2      = (const float*)d_in[5];
    const float* b2        = (const float*)d_in[6];
    const float* mem_out   = (const float*)d_in[7];
    const float* fc_w      = (const float*)d_in[8];
    const float* fc_b      = (const float*)d_in[9];
    const float* tau_adp1  = (const float*)d_in[10];
    const float* tau_m1    = (const float*)d_in[11];
    const float* x2in_w    = (const float*)d_in[12];
    const float* x2in_b    = (const float*)d_in[13];
    const float* rec4in_w  = (const float*)d_in[14];
    const float* rec4in_b  = (const float*)d_in[15];
    const float* in2out_w  = (const float*)d_in[16];
    const float* in2out_b  = (const float*)d_in[17];
    const float* rec4out_w = (const float*)d_in[18];
    const float* rec4out_b = (const float*)d_in[19];
    const float* out2in_w  = (const float*)d_in[20];
    const float* out2in_b  = (const float*)d_in[21];
    const float* tau_adp2  = (const float*)d_in[22];
    const float* tau_m2    = (const float*)d_in[23];
    const float* out_tau_m = (const float*)d_in[24];

    float* out = (float*)d_out;
    const size_t BH = (size_t)NB * NH0;
    float* log_sm    = out;
    float* mem1n     = out + (size_t)NB * NOUT;
    float* spk1n     = mem1n + BH;
    float* b1n       = spk1n + BH;
    float* mem2n     = b1n + BH;
    float* spk2n     = mem2n + BH;
    float* b2n       = spk2n + BH;
    float* mem_out_n = b2n + BH;

    if (g_s2 == nullptr) {
        cudaStreamCreateWithFlags(&g_s2, cudaStreamNonBlocking);
        cudaEventCreateWithFlags(&g_evFork, cudaEventDisableTiming);
        cudaEventCreateWithFlags(&g_evJoin, cudaEventDisableTiming);
    }

    cudaFuncSetAttribute(gemm1_h2_kernel, cudaFuncAttributeMaxDynamicSharedMemorySize,
                         SMEM_G1);
    cudaFuncSetAttribute(gemm2_h2_kernel, cudaFuncAttributeMaxDynamicSharedMemorySize,
                         SMEM_G2);

    // Fork: side stream handles gemm2-only conversions so they overlap gemm1.
    cudaEventRecord(g_evFork, 0);
    cudaStreamWaitEvent(g_s2, g_evFork, 0);
    {
        const long T = 4L * NR * NR + (long)NR * NH0 + NH1;
        convPre2_kernel<<<(int)((T + 255) / 256), 256, 0, g_s2>>>(
            rec4out_w, in2out_w, out2in_w, rec4in_w, x2in_w,
            tau_m2, tau_adp2, rec4out_b, in2out_b, out2in_b, rec4in_b, x2in_b);
    }
    {
        const long T = (long)NB * (NH1 / 2);
        convA_kernel<<<(int)((T + 255) / 256), 256, 0, g_s2>>>(spk2);
    }
    cudaEventRecord(g_evJoin, g_s2);

    // Main stream: gemm1 deps, then gemm1.
    {
        const long T = (long)NH0 * IN_D + (long)NB * IN_D + NH0;
        convPre1_kernel<<<(int)((T + 255) / 256), 256>>>(fc_w, x_t, tau_m1, tau_adp1);
    }
    gemm1_h2_kernel<<<dim3(32, 32), 512, SMEM_G1>>>(
        fc_b, mem1, spk1, b1, mem1n, spk1n, b1n);

    // Join before gemm2 (needs W planes + spk2-half of g_Ah).
    cudaStreamWaitEvent(0, g_evJoin, 0);

    gemm2_h2_kernel<<<dim3(32, 16, 2), 512, SMEM_G2>>>(
        spk2, mem2, b2, mem2n, spk2n, b2n);

    head_kernel<<<NB, 320>>>(spk2n, mem_out, out_tau_m, log_sm, mem_out_n);
}